// round 1
// baseline (speedup 1.0000x reference)
#include <cuda_runtime.h>
#include <math.h>

// Problem constants
#define NN 20000
#define EE 320000
#define BBATCH 16
#define MAXHF 512
#define NEG_SLOPE 0.2f

// ---------------- scratch (static device globals: allocation-free) ----------------
__device__ float g_h[(size_t)NN * MAXHF];    // pre-aggregation features h = x @ W
__device__ float g_out[(size_t)NN * MAXHF];  // aggregated layer output (next layer input)
__device__ float g_as[NN * 4];               // alpha_src per (node, head)
__device__ float g_ad[NN * 4];               // alpha_dst per (node, head)
__device__ float g_m[NN * 4];                // segment max per (dst, head)
__device__ float g_den[NN * 4];              // softmax denominator per (dst, head)
__device__ float g_ex[(size_t)EE * 4];       // exp(e - m[dst]) per (edge, head)
__device__ int   g_flag;                     // any(node_mask)

__device__ __forceinline__ float leakyf(float x) { return x > 0.f ? x : NEG_SLOPE * x; }

__device__ __forceinline__ void atomicMaxF(float* addr, float v) {
    if (v >= 0.f) atomicMax((int*)addr, __float_as_int(v));
    else          atomicMin((unsigned int*)addr, __float_as_uint(v));
}

__device__ __forceinline__ void red_add_v4(float* addr, float4 v) {
    asm volatile("red.global.add.v4.f32 [%0], {%1, %2, %3, %4};"
                 :: "l"(addr), "f"(v.x), "f"(v.y), "f"(v.z), "f"(v.w) : "memory");
}

// ---------------- GEMM: C[M,N] = A[M,K] @ B[K,N], fp32 ----------------
#define GBM 128
#define GBN 64
#define GBK 16

__global__ __launch_bounds__(256)
void gemm_kernel(const float* __restrict__ A, const float* __restrict__ B,
                 float* __restrict__ C, int M, int N, int K) {
    __shared__ float As[GBK][GBM + 4];  // transposed A tile
    __shared__ float Bs[GBK][GBN + 4];

    int tid = threadIdx.x;
    int tx = tid & 15;        // 0..15 (cols)
    int ty = tid >> 4;        // 0..15 (rows)
    int r0 = blockIdx.y * GBM;
    int c0 = blockIdx.x * GBN;

    float acc[8][4];
#pragma unroll
    for (int i = 0; i < 8; i++)
#pragma unroll
        for (int j = 0; j < 4; j++) acc[i][j] = 0.f;

    for (int k0 = 0; k0 < K; k0 += GBK) {
        // Load A tile: 128x16 = 512 float4, 2 per thread
#pragma unroll
        for (int t = 0; t < 2; t++) {
            int id = tid * 2 + t;
            int m  = id >> 2;          // 0..127
            int k4 = (id & 3) * 4;     // 0,4,8,12
            float4 v = make_float4(0.f, 0.f, 0.f, 0.f);
            int row = r0 + m;
            if (row < M) v = *(const float4*)&A[(size_t)row * K + k0 + k4];
            As[k4 + 0][m] = v.x; As[k4 + 1][m] = v.y;
            As[k4 + 2][m] = v.z; As[k4 + 3][m] = v.w;
        }
        // Load B tile: 16x64 = 256 float4, 1 per thread
        {
            int k  = tid >> 4;         // 0..15
            int n4 = (tid & 15) * 4;   // 0..60
            *(float4*)&Bs[k][n4] = *(const float4*)&B[(size_t)(k0 + k) * N + c0 + n4];
        }
        __syncthreads();

#pragma unroll
        for (int kk = 0; kk < GBK; kk++) {
            float a[8], b[4];
            *(float4*)&a[0] = *(const float4*)&As[kk][ty * 8];
            *(float4*)&a[4] = *(const float4*)&As[kk][ty * 8 + 4];
            *(float4*)&b[0] = *(const float4*)&Bs[kk][tx * 4];
#pragma unroll
            for (int i = 0; i < 8; i++)
#pragma unroll
                for (int j = 0; j < 4; j++)
                    acc[i][j] = fmaf(a[i], b[j], acc[i][j]);
        }
        __syncthreads();
    }

#pragma unroll
    for (int i = 0; i < 8; i++) {
        int row = r0 + ty * 8 + i;
        if (row < M) {
#pragma unroll
            for (int j = 0; j < 4; j++)
                C[(size_t)row * N + c0 + tx * 4 + j] = acc[i][j];
        }
    }
}

// ---------------- per-node alpha + self-loop max init (warp per node-head) --------
__global__ void node_prep_kernel(const float* __restrict__ asrc,
                                 const float* __restrict__ adst, int H, int F) {
    int gw   = (blockIdx.x * blockDim.x + threadIdx.x) >> 5;
    int lane = threadIdx.x & 31;
    if (gw >= NN * H) return;
    int node = gw / H, h = gw % H;
    const float* hp = &g_h[(size_t)node * H * F + h * F];
    float s = 0.f, d = 0.f;
    for (int f = lane; f < F; f += 32) {
        float v = hp[f];
        s = fmaf(v, asrc[h * F + f], s);
        d = fmaf(v, adst[h * F + f], d);
    }
#pragma unroll
    for (int o = 16; o; o >>= 1) {
        s += __shfl_xor_sync(0xffffffffu, s, o);
        d += __shfl_xor_sync(0xffffffffu, d, o);
    }
    if (lane == 0) {
        g_as[node * H + h] = s;
        g_ad[node * H + h] = d;
        g_m[node * H + h]  = leakyf(s + d);   // self-loop logit seeds the segment max
    }
}

// ---------------- edge segment max ----------------
__global__ void edge_max_kernel(const int* __restrict__ ei, int H) {
    int idx = blockIdx.x * blockDim.x + threadIdx.x;
    if (idx >= EE * H) return;
    int e = idx / H, h = idx - e * H;
    int src = ei[e], dst = ei[EE + e];
    float ev = leakyf(g_as[src * H + h] + g_ad[dst * H + h]);
    atomicMaxF(&g_m[dst * H + h], ev);
}

// ---------------- denom seed from self loop ----------------
__global__ void node_den_kernel(int H) {
    int idx = blockIdx.x * blockDim.x + threadIdx.x;
    if (idx >= NN * H) return;
    float es = leakyf(g_as[idx] + g_ad[idx]);
    g_den[idx] = expf(es - g_m[idx]);
}

// ---------------- edge exp + denom sum ----------------
__global__ void edge_sum_kernel(const int* __restrict__ ei, int H) {
    int idx = blockIdx.x * blockDim.x + threadIdx.x;
    if (idx >= EE * H) return;
    int e = idx / H, h = idx - e * H;
    int src = ei[e], dst = ei[EE + e];
    float ev = leakyf(g_as[src * H + h] + g_ad[dst * H + h]);
    float ex = expf(ev - g_m[dst * H + h]);
    g_ex[idx] = ex;
    atomicAdd(&g_den[dst * H + h], ex);
}

// ---------------- self-loop aggregation: out = h * w_self (also initializes out) --
__global__ void self_agg_kernel(int H, int F) {
    int node = blockIdx.x;
    int t = threadIdx.x;          // 128 threads
    int HF = H * F;
    int V = HF / 128;             // 4 (H=4) or 1 (H=1)
    int c = t * V;
    int h = c / F;
    int a = node * H + h;
    float w = expf(leakyf(g_as[a] + g_ad[a]) - g_m[a]) / g_den[a];
    size_t base = (size_t)node * HF + c;
    if (V == 4) {
        float4 v = *(const float4*)&g_h[base];
        float4 o = make_float4(v.x * w, v.y * w, v.z * w, v.w * w);
        *(float4*)&g_out[base] = o;
    } else {
        g_out[base] = g_h[base] * w;
    }
}

// ---------------- edge aggregation: warp per (edge, head), red.v4 scatter ---------
__global__ void edge_agg_kernel(const int* __restrict__ ei, int H, int F) {
    int gw   = (blockIdx.x * blockDim.x + threadIdx.x) >> 5;
    int lane = threadIdx.x & 31;
    if (gw >= EE * H) return;
    int e = gw / H, h = gw - e * H;
    int src = ei[e], dst = ei[EE + e];
    float w = g_ex[(size_t)e * H + h] / g_den[dst * H + h];
    int HF = H * F;
    const float4 v = *(const float4*)&g_h[(size_t)src * HF + h * F + lane * 4];
    float4 o = make_float4(v.x * w, v.y * w, v.z * w, v.w * w);
    red_add_v4(&g_out[(size_t)dst * HF + h * F + lane * 4], o);
}

// ---------------- bias + relu ----------------
__global__ void bias_act_kernel(const float* __restrict__ bias, int HF) {
    int idx = blockIdx.x * blockDim.x + threadIdx.x;
    if (idx >= NN * HF) return;
    float v = g_out[idx] + bias[idx % HF];
    g_out[idx] = fmaxf(v, 0.f);
}

// ---------------- mask flag ----------------
__global__ void flag_zero_kernel() { g_flag = 0; }
__global__ void flag_set_kernel(const int* __restrict__ mask) {
    int i = blockIdx.x * blockDim.x + threadIdx.x;
    if (i < NN && mask[i] != 0) g_flag = 1;
}

// ---------------- pooling ----------------
__global__ void pool_init_kernel(float* out) {
    int i = blockIdx.x * blockDim.x + threadIdx.x;
    if (i < BBATCH * 128) out[i] = -1e30f;
}
__global__ void pool_kernel(const float* __restrict__ bias3,
                            const int* __restrict__ batch,
                            const int* __restrict__ mask,
                            float* __restrict__ out) {
    int idx = blockIdx.x * blockDim.x + threadIdx.x;
    if (idx >= NN * 128) return;
    int node = idx >> 7, f = idx & 127;
    if (g_flag && mask[node] != 0) return;   // invalid nodes can never win vs -1e30
    float v = g_out[(size_t)node * 128 + f] + bias3[f];
    atomicMaxF(&out[batch[node] * 128 + f], v);
}

// ---------------- host side ----------------
static inline int cdiv(int a, int b) { return (a + b - 1) / b; }

static void run_layer(const float* x, const float* W, const float* asrc,
                      const float* adst, const float* bias, const int* ei,
                      float* p_h, int Fin, int F, int H, int do_bias_relu) {
    int HF = H * F;
    dim3 ggrid(HF / GBN, cdiv(NN, GBM));
    gemm_kernel<<<ggrid, 256>>>(x, W, p_h, NN, HF, Fin);

    node_prep_kernel<<<cdiv(NN * H * 32, 256), 256>>>(asrc, adst, H, F);
    edge_max_kernel<<<cdiv(EE * H, 256), 256>>>(ei, H);
    node_den_kernel<<<cdiv(NN * H, 256), 256>>>(H);
    edge_sum_kernel<<<cdiv(EE * H, 256), 256>>>(ei, H);
    self_agg_kernel<<<NN, 128>>>(H, F);
    {
        long long total = (long long)EE * H * 32;
        edge_agg_kernel<<<(unsigned)((total + 255) / 256), 256>>>(ei, H, F);
    }
    if (do_bias_relu)
        bias_act_kernel<<<cdiv(NN * HF, 256), 256>>>(bias, HF);
}

extern "C" void kernel_launch(void* const* d_in, const int* in_sizes, int n_in,
                              void* d_out, int out_size) {
    const float* x     = (const float*)d_in[0];
    const int*   ei    = (const int*)d_in[1];
    const int*   batch = (const int*)d_in[2];
    const int*   nmask = (const int*)d_in[3];
    // d_in[4] = edge_mask (ignored by reference: GATConv edge_dim=None)
    const float* W1 = (const float*)d_in[5];
    const float* as1 = (const float*)d_in[6];
    const float* ad1 = (const float*)d_in[7];
    const float* b1 = (const float*)d_in[8];
    const float* W2 = (const float*)d_in[9];
    const float* as2 = (const float*)d_in[10];
    const float* ad2 = (const float*)d_in[11];
    const float* b2 = (const float*)d_in[12];
    const float* W3 = (const float*)d_in[13];
    const float* as3 = (const float*)d_in[14];
    const float* ad3 = (const float*)d_in[15];
    const float* b3 = (const float*)d_in[16];

    float* p_h = nullptr;
    float* p_out = nullptr;
    cudaGetSymbolAddress((void**)&p_h, g_h);
    cudaGetSymbolAddress((void**)&p_out, g_out);

    float* dout = (float*)d_out;

    // Layer 1: in 128, out 4x128, relu
    run_layer(x, W1, as1, ad1, b1, ei, p_h, 128, 128, 4, 1);
    // Layer 2: in 512, out 4x128, relu
    run_layer(p_out, W2, as2, ad2, b2, ei, p_h, 512, 128, 4, 1);
    // Layer 3: in 512, out 1x128, no relu; bias folded into pooling
    run_layer(p_out, W3, as3, ad3, b3, ei, p_h, 512, 128, 1, 0);

    // Masked global max pool
    flag_zero_kernel<<<1, 1>>>();
    flag_set_kernel<<<cdiv(NN, 256), 256>>>(nmask);
    pool_init_kernel<<<cdiv(BBATCH * 128, 256), 256>>>(dout);
    pool_kernel<<<cdiv(NN * 128, 256), 256>>>(b3, batch, nmask, dout);
}

// round 2
// speedup vs baseline: 1.4048x; 1.4048x over previous
#include <cuda_runtime.h>
#include <math.h>

// Problem constants
#define NN 20000
#define EE 320000
#define BBATCH 16
#define NEG_SLOPE 0.2f

// ---------------- scratch (static device globals: allocation-free) ----------------
__device__ float g_h[(size_t)NN * 512];    // pre-aggregation features h = x @ W
__device__ float g_out[(size_t)NN * 512];  // aggregated layer output
__device__ float g_as[NN * 4];             // alpha_src per (node, head)
__device__ float g_ad[NN * 4];             // alpha_dst per (node, head)
__device__ int   g_cnt[NN];                // in-degree counts / scatter cursors
__device__ int   g_rowptr[NN + 1];         // CSR row pointers (by dst)
__device__ int   g_col[EE];                // CSR column (src node ids)
__device__ int   g_flag;                   // any(node_mask)

__device__ __forceinline__ float leakyf(float x) { return x > 0.f ? x : NEG_SLOPE * x; }

__device__ __forceinline__ void atomicMaxF(float* addr, float v) {
    if (v >= 0.f) atomicMax((int*)addr, __float_as_int(v));
    else          atomicMin((unsigned int*)addr, __float_as_uint(v));
}

// ---------------- CSR build ----------------
__global__ void zero_cnt_kernel() {
    int i = blockIdx.x * blockDim.x + threadIdx.x;
    if (i < NN) g_cnt[i] = 0;
}
__global__ void count_kernel(const int* __restrict__ ei) {
    int i = blockIdx.x * blockDim.x + threadIdx.x;
    if (i < EE) atomicAdd(&g_cnt[ei[EE + i]], 1);
}
// single block, 1024 threads, each owns a chunk of 20 nodes
__global__ __launch_bounds__(1024) void scan_kernel() {
    __shared__ int sums[1024];
    const int C = 20;
    int t = threadIdx.x;
    int base = t * C;
    int s = 0;
    for (int i = 0; i < C; i++) {
        int idx = base + i;
        if (idx < NN) s += g_cnt[idx];
    }
    sums[t] = s;
    __syncthreads();
    for (int off = 1; off < 1024; off <<= 1) {
        int v = (t >= off) ? sums[t - off] : 0;
        __syncthreads();
        sums[t] += v;
        __syncthreads();
    }
    int run = (t == 0) ? 0 : sums[t - 1];
    for (int i = 0; i < C; i++) {
        int idx = base + i;
        if (idx < NN) { g_rowptr[idx] = run; run += g_cnt[idx]; }
    }
    if (t == 1023) g_rowptr[NN] = run;
}
__global__ void scatter_kernel(const int* __restrict__ ei) {
    int i = blockIdx.x * blockDim.x + threadIdx.x;
    if (i >= EE) return;
    int dst = ei[EE + i];
    int pos = g_rowptr[dst] + atomicAdd(&g_cnt[dst], 1);
    g_col[pos] = ei[i];
}

// ---------------- SGEMM: C[M,N] = A[M,K] @ B[K,N], fp32, double-buffered --------
#define BM 128
#define BN 128
#define BK 8

__global__ __launch_bounds__(256)
void sgemm_kernel(const float* __restrict__ A, const float* __restrict__ B,
                  float* __restrict__ C, int M, int N, int K) {
    __shared__ float As[2][BK][BM];
    __shared__ float Bs[2][BK][BN];

    int tid = threadIdx.x;
    int tx = tid & 15;     // 0..15
    int ty = tid >> 4;     // 0..15
    int r0 = blockIdx.y * BM;
    int c0 = blockIdx.x * BN;

    // global load mapping
    int arow = tid >> 1;           // 0..127
    int acol = (tid & 1) * 4;      // 0 or 4
    int brow = tid >> 6;           // 0..3 -> need 8 rows? 256 thr, B tile 8x128=1024 floats = 1 float4/thr
    // B: 8 rows x 128 cols: thread -> row = tid/32 (0..7), col4 = (tid%32)*4
    brow = tid >> 5;               // 0..7
    int bcol = (tid & 31) * 4;

    bool arow_ok = (r0 + arow) < M;
    const float* Aptr = A + (size_t)(r0 + arow) * K + acol;
    const float* Bptr = B + (size_t)brow * N + c0 + bcol;

    float acc[8][8];
#pragma unroll
    for (int i = 0; i < 8; i++)
#pragma unroll
        for (int j = 0; j < 8; j++) acc[i][j] = 0.f;

    int nT = K / BK;

    // prologue: tile 0
    float4 aReg = arow_ok ? *(const float4*)Aptr : make_float4(0.f, 0.f, 0.f, 0.f);
    float4 bReg = *(const float4*)Bptr;
    {
        float* ar = (float*)&aReg;
#pragma unroll
        for (int i = 0; i < 4; i++) As[0][acol + i][arow] = ar[i];
        *(float4*)&Bs[0][brow][bcol] = bReg;
    }
    __syncthreads();

    int cur = 0;
    for (int t = 0; t < nT; t++) {
        if (t + 1 < nT) {
            const float* ap = Aptr + (size_t)(t + 1) * BK;
            const float* bp = Bptr + (size_t)(t + 1) * BK * N;
            aReg = arow_ok ? *(const float4*)ap : make_float4(0.f, 0.f, 0.f, 0.f);
            bReg = *(const float4*)bp;
        }
#pragma unroll
        for (int kk = 0; kk < BK; kk++) {
            float a[8], b[8];
            *(float4*)&a[0] = *(const float4*)&As[cur][kk][ty * 8];
            *(float4*)&a[4] = *(const float4*)&As[cur][kk][ty * 8 + 4];
            *(float4*)&b[0] = *(const float4*)&Bs[cur][kk][tx * 8];
            *(float4*)&b[4] = *(const float4*)&Bs[cur][kk][tx * 8 + 4];
#pragma unroll
            for (int i = 0; i < 8; i++)
#pragma unroll
                for (int j = 0; j < 8; j++)
                    acc[i][j] = fmaf(a[i], b[j], acc[i][j]);
        }
        if (t + 1 < nT) {
            int nxt = cur ^ 1;
            float* ar = (float*)&aReg;
#pragma unroll
            for (int i = 0; i < 4; i++) As[nxt][acol + i][arow] = ar[i];
            *(float4*)&Bs[nxt][brow][bcol] = bReg;
        }
        __syncthreads();
        cur ^= 1;
    }

#pragma unroll
    for (int i = 0; i < 8; i++) {
        int row = r0 + ty * 8 + i;
        if (row < M) {
            *(float4*)&C[(size_t)row * N + c0 + tx * 8]     = *(float4*)&acc[i][0];
            *(float4*)&C[(size_t)row * N + c0 + tx * 8 + 4] = *(float4*)&acc[i][4];
        }
    }
}

// ---------------- per-node alpha (warp per node-head) ----------------
__global__ void node_prep_kernel(const float* __restrict__ asrc,
                                 const float* __restrict__ adst, int H, int F) {
    int gw   = (blockIdx.x * blockDim.x + threadIdx.x) >> 5;
    int lane = threadIdx.x & 31;
    if (gw >= NN * H) return;
    int node = gw / H, h = gw % H;
    const float* hp = &g_h[(size_t)node * H * F + h * F];
    float s = 0.f, d = 0.f;
    for (int f = lane; f < F; f += 32) {
        float v = hp[f];
        s = fmaf(v, asrc[h * F + f], s);
        d = fmaf(v, adst[h * F + f], d);
    }
#pragma unroll
    for (int o = 16; o; o >>= 1) {
        s += __shfl_xor_sync(0xffffffffu, s, o);
        d += __shfl_xor_sync(0xffffffffu, d, o);
    }
    if (lane == 0) {
        g_as[node * H + h] = s;
        g_ad[node * H + h] = d;
    }
}

// ---------------- fused attention softmax + aggregation: warp per (dst, head) ----
__global__ __launch_bounds__(256)
void gat_agg_kernel(const float* __restrict__ bias, int H, int F, int relu) {
    int gw   = (blockIdx.x * blockDim.x + threadIdx.x) >> 5;
    int lane = threadIdx.x & 31;
    if (gw >= NN * H) return;
    int dst = gw / H, h = gw - dst * H;
    int HF = H * F;

    int r0 = g_rowptr[dst], r1 = g_rowptr[dst + 1];
    float ad_d   = g_ad[dst * H + h];
    float self_e = leakyf(g_as[dst * H + h] + ad_d);

    // pass 1: segment max (self loop seeds)
    float m = self_e;
    for (int j = r0 + lane; j < r1; j += 32) {
        int s = g_col[j];
        m = fmaxf(m, leakyf(g_as[s * H + h] + ad_d));
    }
#pragma unroll
    for (int o = 16; o; o >>= 1) m = fmaxf(m, __shfl_xor_sync(0xffffffffu, m, o));

    // pass 2: denominator
    float den = (lane == 0) ? __expf(self_e - m) : 0.f;
    for (int j = r0 + lane; j < r1; j += 32) {
        int s = g_col[j];
        den += __expf(leakyf(g_as[s * H + h] + ad_d) - m);
    }
#pragma unroll
    for (int o = 16; o; o >>= 1) den += __shfl_xor_sync(0xffffffffu, den, o);
    float inv = 1.f / den;

    // pass 3: weighted aggregation, 4 features per lane
    size_t fofs = (size_t)h * F + lane * 4;
    float wS = __expf(self_e - m) * inv;
    float4 acc;
    {
        float4 v = *(const float4*)&g_h[(size_t)dst * HF + fofs];
        acc = make_float4(v.x * wS, v.y * wS, v.z * wS, v.w * wS);
    }
    int j = r0;
    for (; j + 2 <= r1; j += 2) {
        int s0 = g_col[j], s1 = g_col[j + 1];
        float e0 = leakyf(g_as[s0 * H + h] + ad_d);
        float e1 = leakyf(g_as[s1 * H + h] + ad_d);
        float4 v0 = *(const float4*)&g_h[(size_t)s0 * HF + fofs];
        float4 v1 = *(const float4*)&g_h[(size_t)s1 * HF + fofs];
        float w0 = __expf(e0 - m) * inv;
        float w1 = __expf(e1 - m) * inv;
        acc.x += v0.x * w0 + v1.x * w1;
        acc.y += v0.y * w0 + v1.y * w1;
        acc.z += v0.z * w0 + v1.z * w1;
        acc.w += v0.w * w0 + v1.w * w1;
    }
    if (j < r1) {
        int s0 = g_col[j];
        float w0 = __expf(leakyf(g_as[s0 * H + h] + ad_d) - m) * inv;
        float4 v0 = *(const float4*)&g_h[(size_t)s0 * HF + fofs];
        acc.x += v0.x * w0; acc.y += v0.y * w0; acc.z += v0.z * w0; acc.w += v0.w * w0;
    }

    // bias + optional relu
    float4 b4 = *(const float4*)&bias[h * F + lane * 4];
    acc.x += b4.x; acc.y += b4.y; acc.z += b4.z; acc.w += b4.w;
    if (relu) {
        acc.x = fmaxf(acc.x, 0.f); acc.y = fmaxf(acc.y, 0.f);
        acc.z = fmaxf(acc.z, 0.f); acc.w = fmaxf(acc.w, 0.f);
    }
    *(float4*)&g_out[(size_t)dst * HF + fofs] = acc;
}

// ---------------- mask flag ----------------
__global__ void flag_zero_kernel() { g_flag = 0; }
__global__ void flag_set_kernel(const int* __restrict__ mask) {
    int i = blockIdx.x * blockDim.x + threadIdx.x;
    if (i < NN && mask[i] != 0) g_flag = 1;
}

// ---------------- pooling ----------------
__global__ void pool_init_kernel(float* out) {
    int i = blockIdx.x * blockDim.x + threadIdx.x;
    if (i < BBATCH * 128) out[i] = -1e30f;
}
__global__ void pool_kernel(const int* __restrict__ batch,
                            const int* __restrict__ mask,
                            float* __restrict__ out) {
    int idx = blockIdx.x * blockDim.x + threadIdx.x;
    if (idx >= NN * 128) return;
    int node = idx >> 7, f = idx & 127;
    if (g_flag && mask[node] != 0) return;
    float v = g_out[(size_t)node * 128 + f];
    atomicMaxF(&out[batch[node] * 128 + f], v);
}

// ---------------- host side ----------------
static inline int cdiv(int a, int b) { return (a + b - 1) / b; }

static void run_layer(const float* x, const float* W, const float* asrc,
                      const float* adst, const float* bias,
                      float* p_h, int Fin, int F, int H, int relu) {
    int HF = H * F;
    dim3 ggrid(HF / BN, cdiv(NN, BM));
    sgemm_kernel<<<ggrid, 256>>>(x, W, p_h, NN, HF, Fin);
    node_prep_kernel<<<cdiv(NN * H * 32, 256), 256>>>(asrc, adst, H, F);
    gat_agg_kernel<<<cdiv(NN * H * 32, 256), 256>>>(bias, H, F, relu);
}

extern "C" void kernel_launch(void* const* d_in, const int* in_sizes, int n_in,
                              void* d_out, int out_size) {
    const float* x     = (const float*)d_in[0];
    const int*   ei    = (const int*)d_in[1];
    const int*   batch = (const int*)d_in[2];
    const int*   nmask = (const int*)d_in[3];
    // d_in[4] = edge_mask (ignored: GATConv edge_dim=None)
    const float* W1 = (const float*)d_in[5];
    const float* as1 = (const float*)d_in[6];
    const float* ad1 = (const float*)d_in[7];
    const float* b1 = (const float*)d_in[8];
    const float* W2 = (const float*)d_in[9];
    const float* as2 = (const float*)d_in[10];
    const float* ad2 = (const float*)d_in[11];
    const float* b2 = (const float*)d_in[12];
    const float* W3 = (const float*)d_in[13];
    const float* as3 = (const float*)d_in[14];
    const float* ad3 = (const float*)d_in[15];
    const float* b3 = (const float*)d_in[16];

    float* p_h = nullptr;
    float* p_out = nullptr;
    cudaGetSymbolAddress((void**)&p_h, g_h);
    cudaGetSymbolAddress((void**)&p_out, g_out);
    float* dout = (float*)d_out;

    // CSR build (by dst); deterministic per call, graph-capturable
    zero_cnt_kernel<<<cdiv(NN, 256), 256>>>();
    count_kernel<<<cdiv(EE, 256), 256>>>(ei);
    scan_kernel<<<1, 1024>>>();
    zero_cnt_kernel<<<cdiv(NN, 256), 256>>>();
    scatter_kernel<<<cdiv(EE, 256), 256>>>(ei);

    // Layer 1: in 128 -> 4x128, relu
    run_layer(x, W1, as1, ad1, b1, p_h, 128, 128, 4, 1);
    // Layer 2: in 512 -> 4x128, relu
    run_layer(p_out, W2, as2, ad2, b2, p_h, 512, 128, 4, 1);
    // Layer 3: in 512 -> 1x128, no relu (bias fused in agg)
    run_layer(p_out, W3, as3, ad3, b3, p_h, 512, 128, 1, 0);

    // Masked global max pool
    flag_zero_kernel<<<1, 1>>>();
    flag_set_kernel<<<cdiv(NN, 256), 256>>>(nmask);
    pool_init_kernel<<<cdiv(BBATCH * 128, 256), 256>>>(dout);
    pool_kernel<<<cdiv(NN * 128, 256), 256>>>(batch, nmask, dout);
}

// round 4
// speedup vs baseline: 1.8647x; 1.3274x over previous
#include <cuda_runtime.h>
#include <cuda_bf16.h>
#include <math.h>
#include <stdint.h>

// Problem constants
#define NN 20000
#define EE 320000
#define BBATCH 16
#define NEG_SLOPE 0.2f
#define M_PAD 20096           // 157 * 128

// ---------------- scratch (static device globals: allocation-free) ----------------
__device__ float g_h[(size_t)M_PAD * 512];   // GEMM output h = x @ W (padded rows)
__device__ float g_out[(size_t)NN * 512];    // aggregated layer output
__device__ __nv_bfloat16 g_ah[(size_t)M_PAD * 512];  // activation hi
__device__ __nv_bfloat16 g_al[(size_t)M_PAD * 512];  // activation lo
__device__ __nv_bfloat16 g_bh[512 * 512];    // weight^T hi  [HF, K]
__device__ __nv_bfloat16 g_bl[512 * 512];    // weight^T lo
__device__ float g_as[NN * 4];
__device__ float g_ad[NN * 4];
__device__ int   g_cnt[NN];
__device__ int   g_rowptr[NN + 1];
__device__ int   g_col[EE];
__device__ int   g_flag;

__device__ __forceinline__ float leakyf(float x) { return x > 0.f ? x : NEG_SLOPE * x; }

__device__ __forceinline__ void atomicMaxF(float* addr, float v) {
    if (v >= 0.f) atomicMax((int*)addr, __float_as_int(v));
    else          atomicMin((unsigned int*)addr, __float_as_uint(v));
}

// ================= baseline-PTX tensor-core helpers (sm_80-class, valid on compute_103) =====
__device__ __forceinline__ uint32_t smem_u32(const void* p) {
    uint32_t a;
    asm("{ .reg .u64 t; cvta.to.shared.u64 t, %1; cvt.u32.u64 %0, t; }" : "=r"(a) : "l"(p));
    return a;
}
#define CP_COMMIT() asm volatile("cp.async.commit_group;" ::: "memory")
#define CP_WAIT1()  asm volatile("cp.async.wait_group 1;" ::: "memory")
#define CP_WAIT0()  asm volatile("cp.async.wait_group 0;" ::: "memory")
__device__ __forceinline__ void cpa16(uint32_t dst, const void* src) {
    asm volatile("cp.async.cg.shared.global [%0], [%1], 16;" :: "r"(dst), "l"(src) : "memory");
}
__device__ __forceinline__ void ldm4(uint32_t* r, uint32_t addr) {
    asm volatile("ldmatrix.sync.aligned.m8n8.x4.shared.b16 {%0,%1,%2,%3}, [%4];"
                 : "=r"(r[0]), "=r"(r[1]), "=r"(r[2]), "=r"(r[3]) : "r"(addr));
}
__device__ __forceinline__ void mma_bf16(float* d, const uint32_t* a,
                                         uint32_t b0, uint32_t b1) {
    asm volatile("mma.sync.aligned.m16n8k16.row.col.f32.bf16.bf16.f32 "
                 "{%0,%1,%2,%3}, {%4,%5,%6,%7}, {%8,%9}, {%0,%1,%2,%3};"
                 : "+f"(d[0]), "+f"(d[1]), "+f"(d[2]), "+f"(d[3])
                 : "r"(a[0]), "r"(a[1]), "r"(a[2]), "r"(a[3]), "r"(b0), "r"(b1));
}

// ================= bf16 split GEMM via mma.sync =================
// C[M_PAD, HF] = Ah@Bh^T + Ah@Bl^T + Al@Bh^T.
// A: [M, K] bf16 row-major. Bh/Bl: [HF, K] bf16 (transposed weights, K-major).
// Block 128x128, 8 warps (warp tile 32x64), K-chunk 32, double-buffered cp.async.
#define KC 32
#define PITCH 40   // bf16 elems per smem row (80 B) -> ldmatrix conflict-free

__global__ __launch_bounds__(256)
void mma_gemm_kernel(const __nv_bfloat16* __restrict__ Ah,
                     const __nv_bfloat16* __restrict__ Al,
                     const __nv_bfloat16* __restrict__ Bh,
                     const __nv_bfloat16* __restrict__ Bl,
                     float* __restrict__ C, int K, int HF) {
    __shared__ __nv_bfloat16 sA[2][128 * PITCH];
    __shared__ __nv_bfloat16 sB[2][128 * PITCH];

    int tid  = threadIdx.x;
    int wid  = tid >> 5;
    int lane = tid & 31;
    int m0 = blockIdx.y * 128;
    int n0 = blockIdx.x * 128;
    int wm = (wid & 3) * 32;    // warp M offset within block
    int wn = (wid >> 2) * 64;   // warp N offset within block

    float c[2][8][4];
#pragma unroll
    for (int i = 0; i < 2; i++)
#pragma unroll
        for (int j = 0; j < 8; j++)
#pragma unroll
            for (int q = 0; q < 4; q++) c[i][j][q] = 0.f;

    const int KCH = K / KC;        // chunks per combo
    const int CT  = 3 * KCH;       // total chunks (3 bf16-split combos)

    uint32_t sA0 = smem_u32(&sA[0][0]);
    uint32_t sB0 = smem_u32(&sB[0][0]);
    const uint32_t BUFB = 128 * PITCH * 2;  // bytes per buffer

    auto load_chunk = [&](int t, int buf) {
        int combo = t / KCH, kc = t - combo * KCH;
        const __nv_bfloat16* A_ = (combo < 2) ? Ah : Al;
        const __nv_bfloat16* B_ = (combo == 1) ? Bl : Bh;
        const __nv_bfloat16* gA = A_ + (size_t)m0 * K + kc * KC;
        const __nv_bfloat16* gB = B_ + (size_t)n0 * K + kc * KC;
#pragma unroll
        for (int r = 0; r < 2; r++) {
            int i = tid + r * 256;           // 0..511
            int row = i >> 2, seg = i & 3;   // 4 x 16B segments per 32-elem row
            uint32_t so = (uint32_t)(row * PITCH + seg * 8) * 2 + buf * BUFB;
            cpa16(sA0 + so, gA + (size_t)row * K + seg * 8);
            cpa16(sB0 + so, gB + (size_t)row * K + seg * 8);
        }
        CP_COMMIT();
    };

    load_chunk(0, 0);
    if (CT > 1) load_chunk(1, 1);

    for (int t = 0; t < CT; t++) {
        int buf = t & 1;
        if (t + 1 < CT) CP_WAIT1(); else CP_WAIT0();
        __syncthreads();

        uint32_t bA = sA0 + buf * BUFB;
        uint32_t bB = sB0 + buf * BUFB;
        int lr = lane & 15, ls = (lane >> 4) * 8;
#pragma unroll
        for (int ks = 0; ks < 2; ks++) {    // two k16 steps per chunk
            int k0 = ks * 16;
            uint32_t a[2][4], bt[4][4];
#pragma unroll
            for (int mi = 0; mi < 2; mi++)
                ldm4(a[mi], bA + (uint32_t)((wm + mi * 16 + lr) * PITCH + k0 + ls) * 2);
#pragma unroll
            for (int ni = 0; ni < 4; ni++)
                ldm4(bt[ni], bB + (uint32_t)((wn + ni * 16 + lr) * PITCH + k0 + ls) * 2);
#pragma unroll
            for (int mi = 0; mi < 2; mi++)
#pragma unroll
                for (int ni = 0; ni < 4; ni++) {
                    mma_bf16(c[mi][ni * 2],     a[mi], bt[ni][0], bt[ni][2]);
                    mma_bf16(c[mi][ni * 2 + 1], a[mi], bt[ni][1], bt[ni][3]);
                }
        }
        __syncthreads();
        if (t + 2 < CT) load_chunk(t + 2, buf);
    }

    // epilogue: fragment -> global (float2 stores)
#pragma unroll
    for (int mi = 0; mi < 2; mi++) {
        int row = m0 + wm + mi * 16 + (lane >> 2);
#pragma unroll
        for (int ni = 0; ni < 8; ni++) {
            int col = n0 + wn + ni * 8 + (lane & 3) * 2;
            *(float2*)&C[(size_t)row * HF + col]       = make_float2(c[mi][ni][0], c[mi][ni][1]);
            *(float2*)&C[(size_t)(row + 8) * HF + col] = make_float2(c[mi][ni][2], c[mi][ni][3]);
        }
    }
}

// ================= fp32 -> bf16 hi/lo conversions =================
__global__ void conv_act_kernel(const float* __restrict__ src, int total) {
    int i = blockIdx.x * blockDim.x + threadIdx.x;
    if (i >= total) return;
    float v = src[i];
    __nv_bfloat16 h = __float2bfloat16(v);
    g_ah[i] = h;
    g_al[i] = __float2bfloat16(v - __bfloat162float(h));
}
// W: [K, HF] -> g_bh/g_bl: [HF, K]
__global__ void conv_wt_kernel(const float* __restrict__ W, int K, int HF) {
    int i = blockIdx.x * blockDim.x + threadIdx.x;
    if (i >= K * HF) return;
    int k = i / HF, n = i - k * HF;
    float v = W[i];
    __nv_bfloat16 h = __float2bfloat16(v);
    g_bh[(size_t)n * K + k] = h;
    g_bl[(size_t)n * K + k] = __float2bfloat16(v - __bfloat162float(h));
}

// ---------------- CSR build ----------------
__global__ void zero_cnt_kernel() {
    int i = blockIdx.x * blockDim.x + threadIdx.x;
    if (i < NN) g_cnt[i] = 0;
}
__global__ void count_kernel(const int* __restrict__ ei) {
    int i = blockIdx.x * blockDim.x + threadIdx.x;
    if (i < EE) atomicAdd(&g_cnt[ei[EE + i]], 1);
}
__global__ __launch_bounds__(1024) void scan_kernel() {
    __shared__ int sums[1024];
    const int C = 20;
    int t = threadIdx.x;
    int base = t * C;
    int s = 0;
    for (int i = 0; i < C; i++) {
        int idx = base + i;
        if (idx < NN) s += g_cnt[idx];
    }
    sums[t] = s;
    __syncthreads();
    for (int off = 1; off < 1024; off <<= 1) {
        int v = (t >= off) ? sums[t - off] : 0;
        __syncthreads();
        sums[t] += v;
        __syncthreads();
    }
    int run = (t == 0) ? 0 : sums[t - 1];
    for (int i = 0; i < C; i++) {
        int idx = base + i;
        if (idx < NN) { g_rowptr[idx] = run; run += g_cnt[idx]; }
    }
    if (t == 1023) g_rowptr[NN] = run;
}
__global__ void scatter_kernel(const int* __restrict__ ei) {
    int i = blockIdx.x * blockDim.x + threadIdx.x;
    if (i >= EE) return;
    int dst = ei[EE + i];
    int pos = g_rowptr[dst] + atomicAdd(&g_cnt[dst], 1);
    g_col[pos] = ei[i];
}

// ---------------- per-node alpha (warp per node-head) ----------------
__global__ void node_prep_kernel(const float* __restrict__ asrc,
                                 const float* __restrict__ adst, int H, int F) {
    int gw   = (blockIdx.x * blockDim.x + threadIdx.x) >> 5;
    int lane = threadIdx.x & 31;
    if (gw >= NN * H) return;
    int node = gw / H, h = gw % H;
    const float* hp = &g_h[(size_t)node * H * F + h * F];
    float s = 0.f, d = 0.f;
    for (int f = lane; f < F; f += 32) {
        float v = hp[f];
        s = fmaf(v, asrc[h * F + f], s);
        d = fmaf(v, adst[h * F + f], d);
    }
#pragma unroll
    for (int o = 16; o; o >>= 1) {
        s += __shfl_xor_sync(0xffffffffu, s, o);
        d += __shfl_xor_sync(0xffffffffu, d, o);
    }
    if (lane == 0) {
        g_as[node * H + h] = s;
        g_ad[node * H + h] = d;
    }
}

// ---------------- fused softmax + aggregation: warp per (dst, head) ----------
__global__ __launch_bounds__(256)
void gat_agg_kernel(const float* __restrict__ bias, int H, int F, int relu) {
    int gw   = (blockIdx.x * blockDim.x + threadIdx.x) >> 5;
    int lane = threadIdx.x & 31;
    if (gw >= NN * H) return;
    int dst = gw / H, h = gw - dst * H;
    int HF = H * F;

    int r0 = g_rowptr[dst], r1 = g_rowptr[dst + 1];
    float ad_d   = g_ad[dst * H + h];
    float self_e = leakyf(g_as[dst * H + h] + ad_d);

    float m = self_e;
    for (int j = r0 + lane; j < r1; j += 32) {
        int s = g_col[j];
        m = fmaxf(m, leakyf(g_as[s * H + h] + ad_d));
    }
#pragma unroll
    for (int o = 16; o; o >>= 1) m = fmaxf(m, __shfl_xor_sync(0xffffffffu, m, o));

    float den = (lane == 0) ? __expf(self_e - m) : 0.f;
    for (int j = r0 + lane; j < r1; j += 32) {
        int s = g_col[j];
        den += __expf(leakyf(g_as[s * H + h] + ad_d) - m);
    }
#pragma unroll
    for (int o = 16; o; o >>= 1) den += __shfl_xor_sync(0xffffffffu, den, o);
    float inv = 1.f / den;

    size_t fofs = (size_t)h * F + lane * 4;
    float wS = __expf(self_e - m) * inv;
    float4 acc;
    {
        float4 v = *(const float4*)&g_h[(size_t)dst * HF + fofs];
        acc = make_float4(v.x * wS, v.y * wS, v.z * wS, v.w * wS);
    }
    int j = r0;
    for (; j + 2 <= r1; j += 2) {
        int s0 = g_col[j], s1 = g_col[j + 1];
        float e0 = leakyf(g_as[s0 * H + h] + ad_d);
        float e1 = leakyf(g_as[s1 * H + h] + ad_d);
        float4 v0 = *(const float4*)&g_h[(size_t)s0 * HF + fofs];
        float4 v1 = *(const float4*)&g_h[(size_t)s1 * HF + fofs];
        float w0 = __expf(e0 - m) * inv;
        float w1 = __expf(e1 - m) * inv;
        acc.x += v0.x * w0 + v1.x * w1;
        acc.y += v0.y * w0 + v1.y * w1;
        acc.z += v0.z * w0 + v1.z * w1;
        acc.w += v0.w * w0 + v1.w * w1;
    }
    if (j < r1) {
        int s0 = g_col[j];
        float w0 = __expf(leakyf(g_as[s0 * H + h] + ad_d) - m) * inv;
        float4 v0 = *(const float4*)&g_h[(size_t)s0 * HF + fofs];
        acc.x += v0.x * w0; acc.y += v0.y * w0; acc.z += v0.z * w0; acc.w += v0.w * w0;
    }

    float4 b4 = *(const float4*)&bias[h * F + lane * 4];
    acc.x += b4.x; acc.y += b4.y; acc.z += b4.z; acc.w += b4.w;
    if (relu) {
        acc.x = fmaxf(acc.x, 0.f); acc.y = fmaxf(acc.y, 0.f);
        acc.z = fmaxf(acc.z, 0.f); acc.w = fmaxf(acc.w, 0.f);
    }
    *(float4*)&g_out[(size_t)dst * HF + fofs] = acc;
}

// ---------------- mask flag + pooling ----------------
__global__ void flag_zero_kernel() { g_flag = 0; }
__global__ void flag_set_kernel(const int* __restrict__ mask) {
    int i = blockIdx.x * blockDim.x + threadIdx.x;
    if (i < NN && mask[i] != 0) g_flag = 1;
}
__global__ void pool_init_kernel(float* out) {
    int i = blockIdx.x * blockDim.x + threadIdx.x;
    if (i < BBATCH * 128) out[i] = -1e30f;
}
__global__ void pool_kernel(const int* __restrict__ batch,
                            const int* __restrict__ mask,
                            float* __restrict__ out) {
    int idx = blockIdx.x * blockDim.x + threadIdx.x;
    if (idx >= NN * 128) return;
    int node = idx >> 7, f = idx & 127;
    if (g_flag && mask[node] != 0) return;
    float v = g_out[(size_t)node * 128 + f];
    atomicMaxF(&out[batch[node] * 128 + f], v);
}

// ---------------- host side ----------------
static inline int cdiv(int a, int b) { return (a + b - 1) / b; }

static void run_layer(const float* x, const float* W, const float* asrc,
                      const float* adst, const float* bias,
                      float* p_h, int Fin, int F, int H, int relu) {
    int HF = H * F;
    conv_act_kernel<<<cdiv(NN * Fin, 256), 256>>>(x, NN * Fin);
    conv_wt_kernel<<<cdiv(Fin * HF, 256), 256>>>(W, Fin, HF);
    {
        __nv_bfloat16 *pah, *pal, *pbh, *pbl;
        cudaGetSymbolAddress((void**)&pah, g_ah);
        cudaGetSymbolAddress((void**)&pal, g_al);
        cudaGetSymbolAddress((void**)&pbh, g_bh);
        cudaGetSymbolAddress((void**)&pbl, g_bl);
        dim3 grid(HF / 128, M_PAD / 128);
        mma_gemm_kernel<<<grid, 256>>>(pah, pal, pbh, pbl, p_h, Fin, HF);
    }
    node_prep_kernel<<<cdiv(NN * H * 32, 256), 256>>>(asrc, adst, H, F);
    gat_agg_kernel<<<cdiv(NN * H * 32, 256), 256>>>(bias, H, F, relu);
}

extern "C" void kernel_launch(void* const* d_in, const int* in_sizes, int n_in,
                              void* d_out, int out_size) {
    const float* x     = (const float*)d_in[0];
    const int*   ei    = (const int*)d_in[1];
    const int*   batch = (const int*)d_in[2];
    const int*   nmask = (const int*)d_in[3];
    // d_in[4] = edge_mask (ignored: GATConv edge_dim=None)
    const float* W1 = (const float*)d_in[5];
    const float* as1 = (const float*)d_in[6];
    const float* ad1 = (const float*)d_in[7];
    const float* b1 = (const float*)d_in[8];
    const float* W2 = (const float*)d_in[9];
    const float* as2 = (const float*)d_in[10];
    const float* ad2 = (const float*)d_in[11];
    const float* b2 = (const float*)d_in[12];
    const float* W3 = (const float*)d_in[13];
    const float* as3 = (const float*)d_in[14];
    const float* ad3 = (const float*)d_in[15];
    const float* b3 = (const float*)d_in[16];

    float* p_h = nullptr;
    float* p_out = nullptr;
    cudaGetSymbolAddress((void**)&p_h, g_h);
    cudaGetSymbolAddress((void**)&p_out, g_out);
    float* dout = (float*)d_out;

    // CSR build (by dst)
    zero_cnt_kernel<<<cdiv(NN, 256), 256>>>();
    count_kernel<<<cdiv(EE, 256), 256>>>(ei);
    scan_kernel<<<1, 1024>>>();
    zero_cnt_kernel<<<cdiv(NN, 256), 256>>>();
    scatter_kernel<<<cdiv(EE, 256), 256>>>(ei);

    // Layer 1: in 128 -> 4x128, relu
    run_layer(x, W1, as1, ad1, b1, p_h, 128, 128, 4, 1);
    // Layer 2: in 512 -> 4x128, relu
    run_layer(p_out, W2, as2, ad2, b2, p_h, 512, 128, 4, 1);
    // Layer 3: in 512 -> 1x128, no relu
    run_layer(p_out, W3, as3, ad3, b3, p_h, 512, 128, 1, 0);

    // Masked global max pool
    flag_zero_kernel<<<1, 1>>>();
    flag_set_kernel<<<cdiv(NN, 256), 256>>>(nmask);
    pool_init_kernel<<<cdiv(BBATCH * 128, 256), 256>>>(dout);
    pool_kernel<<<cdiv(NN * 128, 256), 256>>>(batch, nmask, dout);
}

// round 5
// speedup vs baseline: 2.2123x; 1.1864x over previous
#include <cuda_runtime.h>
#include <cuda_bf16.h>
#include <math.h>
#include <stdint.h>

// Problem constants
#define NN 20000
#define EE 320000
#define BBATCH 16
#define NEG_SLOPE 0.2f
#define M_PAD 20096           // 157 * 128

// ---------------- scratch (static device globals: allocation-free) ----------------
__device__ float g_h[(size_t)M_PAD * 512];   // GEMM output h = x @ W (padded rows)
__device__ float g_out[(size_t)NN * 512];    // aggregated layer output
__device__ __nv_bfloat16 g_ah[(size_t)M_PAD * 512];  // activation hi
__device__ __nv_bfloat16 g_al[(size_t)M_PAD * 512];  // activation lo
__device__ __nv_bfloat16 g_bh[512 * 512];    // weight^T hi  [HF, K]
__device__ __nv_bfloat16 g_bl[512 * 512];    // weight^T lo
__device__ float g_as[NN * 4];
__device__ float g_ad[NN * 4];
__device__ int   g_cnt[NN];
__device__ int   g_rowptr[NN + 1];
__device__ int   g_col[EE];
__device__ int   g_flag;

__device__ __forceinline__ float leakyf(float x) { return x > 0.f ? x : NEG_SLOPE * x; }

__device__ __forceinline__ void atomicMaxF(float* addr, float v) {
    if (v >= 0.f) atomicMax((int*)addr, __float_as_int(v));
    else          atomicMin((unsigned int*)addr, __float_as_uint(v));
}

// ================= baseline-PTX tensor-core helpers =================
__device__ __forceinline__ uint32_t smem_u32(const void* p) {
    uint32_t a;
    asm("{ .reg .u64 t; cvta.to.shared.u64 t, %1; cvt.u32.u64 %0, t; }" : "=r"(a) : "l"(p));
    return a;
}
#define CP_COMMIT() asm volatile("cp.async.commit_group;" ::: "memory")
#define CP_WAIT1()  asm volatile("cp.async.wait_group 1;" ::: "memory")
#define CP_WAIT0()  asm volatile("cp.async.wait_group 0;" ::: "memory")
__device__ __forceinline__ void cpa16(uint32_t dst, const void* src) {
    asm volatile("cp.async.cg.shared.global [%0], [%1], 16;" :: "r"(dst), "l"(src) : "memory");
}
__device__ __forceinline__ void ldm4(uint32_t* r, uint32_t addr) {
    asm volatile("ldmatrix.sync.aligned.m8n8.x4.shared.b16 {%0,%1,%2,%3}, [%4];"
                 : "=r"(r[0]), "=r"(r[1]), "=r"(r[2]), "=r"(r[3]) : "r"(addr));
}
__device__ __forceinline__ void mma_bf16(float* d, const uint32_t* a,
                                         uint32_t b0, uint32_t b1) {
    asm volatile("mma.sync.aligned.m16n8k16.row.col.f32.bf16.bf16.f32 "
                 "{%0,%1,%2,%3}, {%4,%5,%6,%7}, {%8,%9}, {%0,%1,%2,%3};"
                 : "+f"(d[0]), "+f"(d[1]), "+f"(d[2]), "+f"(d[3])
                 : "r"(a[0]), "r"(a[1]), "r"(a[2]), "r"(a[3]), "r"(b0), "r"(b1));
}

// ================= bf16 split GEMM via mma.sync, fused 3-term =================
// C = Ah@Bh^T + Ah@Bl^T + Al@Bh^T, all three terms per K-chunk into one accumulator.
// Block 128x128, 8 warps (warp tile 32x64), K-chunk 32, double-buffered cp.async.
// Dynamic smem: 8 tiles (buf x {Ah,Al,Bh,Bl}), each 128 x PITCH bf16.
#define KC 32
#define PITCH 40                 // 80 B rows -> ldmatrix conflict-free
#define TILEB (128 * PITCH * 2)  // 10240 bytes per tile
#define GEMM_SMEM (8 * TILEB)    // 81920

__global__ __launch_bounds__(256)
void mma_gemm_kernel(const __nv_bfloat16* __restrict__ Ah,
                     const __nv_bfloat16* __restrict__ Al,
                     const __nv_bfloat16* __restrict__ Bh,
                     const __nv_bfloat16* __restrict__ Bl,
                     float* __restrict__ C, int K, int HF) {
    extern __shared__ __align__(16) __nv_bfloat16 smem[];
    uint32_t s0 = smem_u32(smem);

    int tid  = threadIdx.x;
    int wid  = tid >> 5;
    int lane = tid & 31;
    int m0 = blockIdx.y * 128;
    int n0 = blockIdx.x * 128;
    int wm = (wid & 3) * 32;    // warp M offset
    int wn = (wid >> 2) * 64;   // warp N offset

    float c[2][8][4];
#pragma unroll
    for (int i = 0; i < 2; i++)
#pragma unroll
        for (int j = 0; j < 8; j++)
#pragma unroll
            for (int q = 0; q < 4; q++) c[i][j][q] = 0.f;

    const int KCH = K / KC;

    const __nv_bfloat16* gp0 = Ah + (size_t)m0 * K;
    const __nv_bfloat16* gp1 = Al + (size_t)m0 * K;
    const __nv_bfloat16* gp2 = Bh + (size_t)n0 * K;
    const __nv_bfloat16* gp3 = Bl + (size_t)n0 * K;

    auto load_chunk = [&](int kc, int buf) {
        const __nv_bfloat16* gp[4] = {gp0 + kc * KC, gp1 + kc * KC,
                                      gp2 + kc * KC, gp3 + kc * KC};
#pragma unroll
        for (int kind = 0; kind < 4; kind++) {
            uint32_t base = s0 + (uint32_t)(buf * 4 + kind) * TILEB;
            const __nv_bfloat16* g = gp[kind];
#pragma unroll
            for (int r = 0; r < 2; r++) {
                int i = tid + r * 256;           // 0..511
                int row = i >> 2, seg = i & 3;   // 4 x 16B per 32-elem row
                cpa16(base + (uint32_t)(row * PITCH + seg * 8) * 2,
                      g + (size_t)row * K + seg * 8);
            }
        }
        CP_COMMIT();
    };

    load_chunk(0, 0);
    if (KCH > 1) load_chunk(1, 1);

    int lr = lane & 15, ls = (lane >> 4) * 8;
    for (int t = 0; t < KCH; t++) {
        int buf = t & 1;
        if (t + 1 < KCH) CP_WAIT1(); else CP_WAIT0();
        __syncthreads();

        uint32_t bAh = s0 + (uint32_t)(buf * 4 + 0) * TILEB;
        uint32_t bAl = s0 + (uint32_t)(buf * 4 + 1) * TILEB;
        uint32_t bBh = s0 + (uint32_t)(buf * 4 + 2) * TILEB;
        uint32_t bBl = s0 + (uint32_t)(buf * 4 + 3) * TILEB;
#pragma unroll
        for (int ks = 0; ks < 2; ks++) {
            int k0 = ks * 16;
            uint32_t ah[2][4], al[2][4], bt[4][4];
#pragma unroll
            for (int mi = 0; mi < 2; mi++)
                ldm4(ah[mi], bAh + (uint32_t)((wm + mi * 16 + lr) * PITCH + k0 + ls) * 2);
#pragma unroll
            for (int mi = 0; mi < 2; mi++)
                ldm4(al[mi], bAl + (uint32_t)((wm + mi * 16 + lr) * PITCH + k0 + ls) * 2);
#pragma unroll
            for (int ni = 0; ni < 4; ni++)
                ldm4(bt[ni], bBh + (uint32_t)((wn + ni * 16 + lr) * PITCH + k0 + ls) * 2);
            // terms Ah·Bh and Al·Bh
#pragma unroll
            for (int mi = 0; mi < 2; mi++)
#pragma unroll
                for (int ni = 0; ni < 4; ni++) {
                    mma_bf16(c[mi][ni * 2],     ah[mi], bt[ni][0], bt[ni][2]);
                    mma_bf16(c[mi][ni * 2 + 1], ah[mi], bt[ni][1], bt[ni][3]);
                    mma_bf16(c[mi][ni * 2],     al[mi], bt[ni][0], bt[ni][2]);
                    mma_bf16(c[mi][ni * 2 + 1], al[mi], bt[ni][1], bt[ni][3]);
                }
            // reload B-low into same regs, term Ah·Bl
#pragma unroll
            for (int ni = 0; ni < 4; ni++)
                ldm4(bt[ni], bBl + (uint32_t)((wn + ni * 16 + lr) * PITCH + k0 + ls) * 2);
#pragma unroll
            for (int mi = 0; mi < 2; mi++)
#pragma unroll
                for (int ni = 0; ni < 4; ni++) {
                    mma_bf16(c[mi][ni * 2],     ah[mi], bt[ni][0], bt[ni][2]);
                    mma_bf16(c[mi][ni * 2 + 1], ah[mi], bt[ni][1], bt[ni][3]);
                }
        }
        __syncthreads();
        if (t + 2 < KCH) load_chunk(t + 2, buf);
    }

    // epilogue: fragment -> global (float2 stores)
#pragma unroll
    for (int mi = 0; mi < 2; mi++) {
        int row = m0 + wm + mi * 16 + (lane >> 2);
#pragma unroll
        for (int ni = 0; ni < 8; ni++) {
            int col = n0 + wn + ni * 8 + (lane & 3) * 2;
            *(float2*)&C[(size_t)row * HF + col]       = make_float2(c[mi][ni][0], c[mi][ni][1]);
            *(float2*)&C[(size_t)(row + 8) * HF + col] = make_float2(c[mi][ni][2], c[mi][ni][3]);
        }
    }
}

// ================= fp32 -> bf16 hi/lo conversions =================
__global__ void conv_act_kernel(const float* __restrict__ src, int total) {
    int i = blockIdx.x * blockDim.x + threadIdx.x;
    if (i >= total) return;
    float v = src[i];
    __nv_bfloat16 h = __float2bfloat16(v);
    g_ah[i] = h;
    g_al[i] = __float2bfloat16(v - __bfloat162float(h));
}
// W: [K, HF] -> g_bh/g_bl: [HF, K]
__global__ void conv_wt_kernel(const float* __restrict__ W, int K, int HF) {
    int i = blockIdx.x * blockDim.x + threadIdx.x;
    if (i >= K * HF) return;
    int k = i / HF, n = i - k * HF;
    float v = W[i];
    __nv_bfloat16 h = __float2bfloat16(v);
    g_bh[(size_t)n * K + k] = h;
    g_bl[(size_t)n * K + k] = __float2bfloat16(v - __bfloat162float(h));
}

// ---------------- CSR build ----------------
__global__ void zero_cnt_kernel() {
    int i = blockIdx.x * blockDim.x + threadIdx.x;
    if (i < NN) g_cnt[i] = 0;
}
__global__ void count_kernel(const int* __restrict__ ei) {
    int i = blockIdx.x * blockDim.x + threadIdx.x;
    if (i < EE) atomicAdd(&g_cnt[ei[EE + i]], 1);
}
__global__ __launch_bounds__(1024) void scan_kernel() {
    __shared__ int sums[1024];
    const int C = 20;
    int t = threadIdx.x;
    int base = t * C;
    int s = 0;
    for (int i = 0; i < C; i++) {
        int idx = base + i;
        if (idx < NN) s += g_cnt[idx];
    }
    sums[t] = s;
    __syncthreads();
    for (int off = 1; off < 1024; off <<= 1) {
        int v = (t >= off) ? sums[t - off] : 0;
        __syncthreads();
        sums[t] += v;
        __syncthreads();
    }
    int run = (t == 0) ? 0 : sums[t - 1];
    for (int i = 0; i < C; i++) {
        int idx = base + i;
        if (idx < NN) { g_rowptr[idx] = run; run += g_cnt[idx]; }
    }
    if (t == 1023) g_rowptr[NN] = run;
}
__global__ void scatter_kernel(const int* __restrict__ ei) {
    int i = blockIdx.x * blockDim.x + threadIdx.x;
    if (i >= EE) return;
    int dst = ei[EE + i];
    int pos = g_rowptr[dst] + atomicAdd(&g_cnt[dst], 1);
    g_col[pos] = ei[i];
}

// ---------------- per-node alpha (warp per node-head) ----------------
__global__ void node_prep_kernel(const float* __restrict__ asrc,
                                 const float* __restrict__ adst, int H, int F) {
    int gw   = (blockIdx.x * blockDim.x + threadIdx.x) >> 5;
    int lane = threadIdx.x & 31;
    if (gw >= NN * H) return;
    int node = gw / H, h = gw % H;
    const float* hp = &g_h[(size_t)node * H * F + h * F];
    float s = 0.f, d = 0.f;
    for (int f = lane; f < F; f += 32) {
        float v = hp[f];
        s = fmaf(v, asrc[h * F + f], s);
        d = fmaf(v, adst[h * F + f], d);
    }
#pragma unroll
    for (int o = 16; o; o >>= 1) {
        s += __shfl_xor_sync(0xffffffffu, s, o);
        d += __shfl_xor_sync(0xffffffffu, d, o);
    }
    if (lane == 0) {
        g_as[node * H + h] = s;
        g_ad[node * H + h] = d;
    }
}

// ------- fused single-pass online-softmax aggregation: warp per (dst, head) -------
// Also (optionally) emits bf16 hi/lo split of the output for the next layer's GEMM.
__global__ __launch_bounds__(256)
void gat_agg_kernel(const float* __restrict__ bias, int H, int F, int relu, int wsplit) {
    int gw   = (blockIdx.x * blockDim.x + threadIdx.x) >> 5;
    int lane = threadIdx.x & 31;
    if (gw >= NN * H) return;
    int dst = gw / H, h = gw - dst * H;
    int HF = H * F;

    int r0 = g_rowptr[dst], r1 = g_rowptr[dst + 1];
    float ad_d = g_ad[dst * H + h];
    float m    = leakyf(g_as[dst * H + h] + ad_d);   // self-loop logit
    float den  = 1.f;                                 // self weight exp(0)

    size_t fofs = (size_t)h * F + lane * 4;
    float4 acc = *(const float4*)&g_h[(size_t)dst * HF + fofs];  // self contribution

    int j = r0;
    for (; j + 2 <= r1; j += 2) {
        int s0 = g_col[j], s1 = g_col[j + 1];
        float e0 = leakyf(g_as[s0 * H + h] + ad_d);
        float e1 = leakyf(g_as[s1 * H + h] + ad_d);
        float4 v0 = *(const float4*)&g_h[(size_t)s0 * HF + fofs];
        float4 v1 = *(const float4*)&g_h[(size_t)s1 * HF + fofs];
        float mn = fmaxf(m, fmaxf(e0, e1));
        float sc = __expf(m - mn);
        float w0 = __expf(e0 - mn);
        float w1 = __expf(e1 - mn);
        den = den * sc + w0 + w1;
        acc.x = acc.x * sc + w0 * v0.x + w1 * v1.x;
        acc.y = acc.y * sc + w0 * v0.y + w1 * v1.y;
        acc.z = acc.z * sc + w0 * v0.z + w1 * v1.z;
        acc.w = acc.w * sc + w0 * v0.w + w1 * v1.w;
        m = mn;
    }
    if (j < r1) {
        int s0 = g_col[j];
        float e0 = leakyf(g_as[s0 * H + h] + ad_d);
        float4 v0 = *(const float4*)&g_h[(size_t)s0 * HF + fofs];
        float mn = fmaxf(m, e0);
        float sc = __expf(m - mn);
        float w0 = __expf(e0 - mn);
        den = den * sc + w0;
        acc.x = acc.x * sc + w0 * v0.x;
        acc.y = acc.y * sc + w0 * v0.y;
        acc.z = acc.z * sc + w0 * v0.z;
        acc.w = acc.w * sc + w0 * v0.w;
        m = mn;
    }

    float inv = 1.f / den;
    float4 b4 = *(const float4*)&bias[h * F + lane * 4];
    acc.x = acc.x * inv + b4.x;
    acc.y = acc.y * inv + b4.y;
    acc.z = acc.z * inv + b4.z;
    acc.w = acc.w * inv + b4.w;
    if (relu) {
        acc.x = fmaxf(acc.x, 0.f); acc.y = fmaxf(acc.y, 0.f);
        acc.z = fmaxf(acc.z, 0.f); acc.w = fmaxf(acc.w, 0.f);
    }
    size_t oidx = (size_t)dst * HF + fofs;
    *(float4*)&g_out[oidx] = acc;

    if (wsplit) {
        __nv_bfloat16 hv[4], lv[4];
        float a[4] = {acc.x, acc.y, acc.z, acc.w};
#pragma unroll
        for (int q = 0; q < 4; q++) {
            hv[q] = __float2bfloat16(a[q]);
            lv[q] = __float2bfloat16(a[q] - __bfloat162float(hv[q]));
        }
        *(uint2*)&g_ah[oidx] = *(uint2*)hv;
        *(uint2*)&g_al[oidx] = *(uint2*)lv;
    }
}

// ---------------- mask flag + pooling ----------------
__global__ void flag_zero_kernel() { g_flag = 0; }
__global__ void flag_set_kernel(const int* __restrict__ mask) {
    int i = blockIdx.x * blockDim.x + threadIdx.x;
    if (i < NN && mask[i] != 0) g_flag = 1;
}
__global__ void pool_init_kernel(float* out) {
    int i = blockIdx.x * blockDim.x + threadIdx.x;
    if (i < BBATCH * 128) out[i] = -1e30f;
}
__global__ void pool_kernel(const int* __restrict__ batch,
                            const int* __restrict__ mask,
                            float* __restrict__ out) {
    int idx = blockIdx.x * blockDim.x + threadIdx.x;
    if (idx >= NN * 128) return;
    int node = idx >> 7, f = idx & 127;
    if (g_flag && mask[node] != 0) return;
    float v = g_out[(size_t)node * 128 + f];
    atomicMaxF(&out[batch[node] * 128 + f], v);
}

// ---------------- host side ----------------
static inline int cdiv(int a, int b) { return (a + b - 1) / b; }

static void run_layer(const float* W, const float* asrc,
                      const float* adst, const float* bias,
                      float* p_h, int Fin, int F, int H, int relu, int wsplit) {
    int HF = H * F;
    conv_wt_kernel<<<cdiv(Fin * HF, 256), 256>>>(W, Fin, HF);
    {
        __nv_bfloat16 *pah, *pal, *pbh, *pbl;
        cudaGetSymbolAddress((void**)&pah, g_ah);
        cudaGetSymbolAddress((void**)&pal, g_al);
        cudaGetSymbolAddress((void**)&pbh, g_bh);
        cudaGetSymbolAddress((void**)&pbl, g_bl);
        dim3 grid(HF / 128, M_PAD / 128);
        mma_gemm_kernel<<<grid, 256, GEMM_SMEM>>>(pah, pal, pbh, pbl, p_h, Fin, HF);
    }
    node_prep_kernel<<<cdiv(NN * H * 32, 256), 256>>>(asrc, adst, H, F);
    gat_agg_kernel<<<cdiv(NN * H * 32, 256), 256>>>(bias, H, F, relu, wsplit);
}

extern "C" void kernel_launch(void* const* d_in, const int* in_sizes, int n_in,
                              void* d_out, int out_size) {
    const float* x     = (const float*)d_in[0];
    const int*   ei    = (const int*)d_in[1];
    const int*   batch = (const int*)d_in[2];
    const int*   nmask = (const int*)d_in[3];
    // d_in[4] = edge_mask (ignored: GATConv edge_dim=None)
    const float* W1 = (const float*)d_in[5];
    const float* as1 = (const float*)d_in[6];
    const float* ad1 = (const float*)d_in[7];
    const float* b1 = (const float*)d_in[8];
    const float* W2 = (const float*)d_in[9];
    const float* as2 = (const float*)d_in[10];
    const float* ad2 = (const float*)d_in[11];
    const float* b2 = (const float*)d_in[12];
    const float* W3 = (const float*)d_in[13];
    const float* as3 = (const float*)d_in[14];
    const float* ad3 = (const float*)d_in[15];
    const float* b3 = (const float*)d_in[16];

    cudaFuncSetAttribute(mma_gemm_kernel,
                         cudaFuncAttributeMaxDynamicSharedMemorySize, GEMM_SMEM);

    float* p_h = nullptr;
    cudaGetSymbolAddress((void**)&p_h, g_h);
    float* dout = (float*)d_out;

    // CSR build (by dst)
    zero_cnt_kernel<<<cdiv(NN, 256), 256>>>();
    count_kernel<<<cdiv(EE, 256), 256>>>(ei);
    scan_kernel<<<1, 1024>>>();
    zero_cnt_kernel<<<cdiv(NN, 256), 256>>>();
    scatter_kernel<<<cdiv(EE, 256), 256>>>(ei);

    // Layer 1: x -> bf16 split, then 128 -> 4x128, relu, emit split for layer 2
    conv_act_kernel<<<cdiv(NN * 128, 256), 256>>>(x, NN * 128);
    run_layer(W1, as1, ad1, b1, p_h, 128, 128, 4, 1, 1);
    // Layer 2: 512 -> 4x128, relu, emit split for layer 3
    run_layer(W2, as2, ad2, b2, p_h, 512, 128, 4, 1, 1);
    // Layer 3: 512 -> 1x128, no relu, no split
    run_layer(W3, as3, ad3, b3, p_h, 512, 128, 1, 0, 0);

    // Masked global max pool
    flag_zero_kernel<<<1, 1>>>();
    flag_set_kernel<<<cdiv(NN, 256), 256>>>(nmask);
    pool_init_kernel<<<cdiv(BBATCH * 128, 256), 256>>>(dout);
    pool_kernel<<<cdiv(NN * 128, 256), 256>>>(batch, nmask, dout);
}

// round 6
// speedup vs baseline: 2.4024x; 1.0859x over previous
#include <cuda_runtime.h>
#include <cuda_bf16.h>
#include <math.h>
#include <stdint.h>

// Problem constants
#define NN 20000
#define EE 320000
#define BBATCH 16
#define NEG_SLOPE 0.2f
#define M_PAD 20096           // 157 * 128

// ---------------- scratch (static device globals: allocation-free) ----------------
__device__ float g_h[(size_t)M_PAD * 512];   // GEMM output h = x @ W (padded rows)
__device__ float g_out[(size_t)NN * 512];    // aggregated layer output
__device__ __nv_bfloat16 g_ah[(size_t)M_PAD * 512];  // activation hi
__device__ __nv_bfloat16 g_al[(size_t)M_PAD * 512];  // activation lo
__device__ __nv_bfloat16 g_bh[512 * 512];    // weight^T hi  [HF, K]
__device__ __nv_bfloat16 g_bl[512 * 512];    // weight^T lo
__device__ float g_as[NN * 4];
__device__ float g_ad[NN * 4];
__device__ int   g_cnt[NN];
__device__ int   g_rowptr[NN + 1];
__device__ int   g_col[EE];
__device__ int   g_flag;

__device__ __forceinline__ float leakyf(float x) { return x > 0.f ? x : NEG_SLOPE * x; }

__device__ __forceinline__ void atomicMaxF(float* addr, float v) {
    if (v >= 0.f) atomicMax((int*)addr, __float_as_int(v));
    else          atomicMin((unsigned int*)addr, __float_as_uint(v));
}

// ================= baseline-PTX tensor-core helpers =================
__device__ __forceinline__ uint32_t smem_u32(const void* p) {
    uint32_t a;
    asm("{ .reg .u64 t; cvta.to.shared.u64 t, %1; cvt.u32.u64 %0, t; }" : "=r"(a) : "l"(p));
    return a;
}
#define CP_COMMIT() asm volatile("cp.async.commit_group;" ::: "memory")
#define CP_WAIT1()  asm volatile("cp.async.wait_group 1;" ::: "memory")
__device__ __forceinline__ void cpa16(uint32_t dst, const void* src) {
    asm volatile("cp.async.cg.shared.global [%0], [%1], 16;" :: "r"(dst), "l"(src) : "memory");
}
__device__ __forceinline__ void ldm4(uint32_t* r, uint32_t addr) {
    asm volatile("ldmatrix.sync.aligned.m8n8.x4.shared.b16 {%0,%1,%2,%3}, [%4];"
                 : "=r"(r[0]), "=r"(r[1]), "=r"(r[2]), "=r"(r[3]) : "r"(addr));
}
__device__ __forceinline__ void mma_bf16(float* d, const uint32_t* a,
                                         uint32_t b0, uint32_t b1) {
    asm volatile("mma.sync.aligned.m16n8k16.row.col.f32.bf16.bf16.f32 "
                 "{%0,%1,%2,%3}, {%4,%5,%6,%7}, {%8,%9}, {%0,%1,%2,%3};"
                 : "+f"(d[0]), "+f"(d[1]), "+f"(d[2]), "+f"(d[3])
                 : "r"(a[0]), "r"(a[1]), "r"(a[2]), "r"(a[3]), "r"(b0), "r"(b1));
}

// ================= bf16 split GEMM (3-term) + fused alpha epilogue ================
// C = Ah@Bh^T + Ah@Bl^T + Al@Bh^T. Block 128x128, 8 warps, K-chunk 32, 3-stage.
// Epilogue also computes alpha_src/alpha_dst for this block's head (block covers
// exactly one head's 128 columns) and stores them -- replaces node_prep.
#define KC 32
#define PITCH 40                 // 80 B rows -> ldmatrix conflict-free
#define TILEB (128 * PITCH * 2)  // 10240 bytes per tile
#define GEMM_SMEM (12 * TILEB)   // 3 stages x 4 tiles = 122880

__global__ __launch_bounds__(256)
void mma_gemm_kernel(const __nv_bfloat16* __restrict__ Ah,
                     const __nv_bfloat16* __restrict__ Al,
                     const __nv_bfloat16* __restrict__ Bh,
                     const __nv_bfloat16* __restrict__ Bl,
                     float* __restrict__ C,
                     const float* __restrict__ asrc,
                     const float* __restrict__ adst,
                     int K, int HF, int H) {
    extern __shared__ __align__(16) __nv_bfloat16 smem[];
    uint32_t s0 = smem_u32(smem);

    int tid  = threadIdx.x;
    int wid  = tid >> 5;
    int lane = tid & 31;
    int m0 = blockIdx.y * 128;
    int n0 = blockIdx.x * 128;
    int wm = (wid & 3) * 32;    // warp M offset
    int wn = (wid >> 2) * 64;   // warp N offset

    float c[2][8][4];
#pragma unroll
    for (int i = 0; i < 2; i++)
#pragma unroll
        for (int j = 0; j < 8; j++)
#pragma unroll
            for (int q = 0; q < 4; q++) c[i][j][q] = 0.f;

    const int KCH = K / KC;

    const __nv_bfloat16* gp0 = Ah + (size_t)m0 * K;
    const __nv_bfloat16* gp1 = Al + (size_t)m0 * K;
    const __nv_bfloat16* gp2 = Bh + (size_t)n0 * K;
    const __nv_bfloat16* gp3 = Bl + (size_t)n0 * K;

    auto load_chunk = [&](int kc, int stage) {
        const __nv_bfloat16* gp[4] = {gp0 + kc * KC, gp1 + kc * KC,
                                      gp2 + kc * KC, gp3 + kc * KC};
#pragma unroll
        for (int kind = 0; kind < 4; kind++) {
            uint32_t base = s0 + (uint32_t)(stage * 4 + kind) * TILEB;
            const __nv_bfloat16* g = gp[kind];
#pragma unroll
            for (int r = 0; r < 2; r++) {
                int i = tid + r * 256;           // 0..511
                int row = i >> 2, seg = i & 3;   // 4 x 16B per 32-elem row
                cpa16(base + (uint32_t)(row * PITCH + seg * 8) * 2,
                      g + (size_t)row * K + seg * 8);
            }
        }
        CP_COMMIT();
    };

    load_chunk(0, 0);
    load_chunk(1, 1);

    int lr = lane & 15, ls = (lane >> 4) * 8;
    for (int t = 0; t < KCH; t++) {
        CP_WAIT1();                // group t complete
        __syncthreads();
        if (t + 2 < KCH) load_chunk(t + 2, (t + 2) % 3);
        else             CP_COMMIT();   // keep group numbering uniform

        int stage = t % 3;
        uint32_t bAh = s0 + (uint32_t)(stage * 4 + 0) * TILEB;
        uint32_t bAl = s0 + (uint32_t)(stage * 4 + 1) * TILEB;
        uint32_t bBh = s0 + (uint32_t)(stage * 4 + 2) * TILEB;
        uint32_t bBl = s0 + (uint32_t)(stage * 4 + 3) * TILEB;
#pragma unroll
        for (int ks = 0; ks < 2; ks++) {
            int k0 = ks * 16;
            uint32_t ah[2][4], al[2][4], bt[4][4];
#pragma unroll
            for (int mi = 0; mi < 2; mi++)
                ldm4(ah[mi], bAh + (uint32_t)((wm + mi * 16 + lr) * PITCH + k0 + ls) * 2);
#pragma unroll
            for (int mi = 0; mi < 2; mi++)
                ldm4(al[mi], bAl + (uint32_t)((wm + mi * 16 + lr) * PITCH + k0 + ls) * 2);
#pragma unroll
            for (int ni = 0; ni < 4; ni++)
                ldm4(bt[ni], bBh + (uint32_t)((wn + ni * 16 + lr) * PITCH + k0 + ls) * 2);
#pragma unroll
            for (int mi = 0; mi < 2; mi++)
#pragma unroll
                for (int ni = 0; ni < 4; ni++) {
                    mma_bf16(c[mi][ni * 2],     ah[mi], bt[ni][0], bt[ni][2]);
                    mma_bf16(c[mi][ni * 2 + 1], ah[mi], bt[ni][1], bt[ni][3]);
                    mma_bf16(c[mi][ni * 2],     al[mi], bt[ni][0], bt[ni][2]);
                    mma_bf16(c[mi][ni * 2 + 1], al[mi], bt[ni][1], bt[ni][3]);
                }
#pragma unroll
            for (int ni = 0; ni < 4; ni++)
                ldm4(bt[ni], bBl + (uint32_t)((wn + ni * 16 + lr) * PITCH + k0 + ls) * 2);
#pragma unroll
            for (int mi = 0; mi < 2; mi++)
#pragma unroll
                for (int ni = 0; ni < 4; ni++) {
                    mma_bf16(c[mi][ni * 2],     ah[mi], bt[ni][0], bt[ni][2]);
                    mma_bf16(c[mi][ni * 2 + 1], ah[mi], bt[ni][1], bt[ni][3]);
                }
        }
    }
    __syncthreads();   // all compute done; smem reusable

    // ---- alpha epilogue: per-thread dot with att vectors, reduce, store ----
    float* ab = (float*)smem;      // 128 rows x {s,d}
    ab[tid] = 0.f;                 // 256 floats
    __syncthreads();
    {
        float ps[2][2] = {{0.f, 0.f}, {0.f, 0.f}};
        float pd[2][2] = {{0.f, 0.f}, {0.f, 0.f}};
#pragma unroll
        for (int ni = 0; ni < 4; ni++) {
#pragma unroll
            for (int q2 = 0; q2 < 2; q2++) {       // the two n8 halves
                int gc = n0 + wn + ni * 16 + q2 * 8 + (lane & 3) * 2;
                float a0 = asrc[gc], a1 = asrc[gc + 1];
                float d0 = adst[gc], d1 = adst[gc + 1];
#pragma unroll
                for (int mi = 0; mi < 2; mi++) {
                    const float* cc = c[mi][ni * 2 + q2];
                    ps[mi][0] += cc[0] * a0 + cc[1] * a1;
                    pd[mi][0] += cc[0] * d0 + cc[1] * d1;
                    ps[mi][1] += cc[2] * a0 + cc[3] * a1;
                    pd[mi][1] += cc[2] * d0 + cc[3] * d1;
                }
            }
        }
#pragma unroll
        for (int o = 1; o <= 2; o <<= 1)
#pragma unroll
            for (int mi = 0; mi < 2; mi++)
#pragma unroll
                for (int hf = 0; hf < 2; hf++) {
                    ps[mi][hf] += __shfl_xor_sync(0xffffffffu, ps[mi][hf], o);
                    pd[mi][hf] += __shfl_xor_sync(0xffffffffu, pd[mi][hf], o);
                }
        if ((lane & 3) == 0) {
#pragma unroll
            for (int mi = 0; mi < 2; mi++)
#pragma unroll
                for (int hf = 0; hf < 2; hf++) {
                    int row = wm + mi * 16 + (lane >> 2) + hf * 8;
                    atomicAdd(&ab[row * 2],     ps[mi][hf]);
                    atomicAdd(&ab[row * 2 + 1], pd[mi][hf]);
                }
        }
    }
    __syncthreads();
    if (tid < 128) {
        int grow = m0 + tid;
        if (grow < NN) {
            int head = n0 >> 7;
            g_as[grow * H + head] = ab[tid * 2];
            g_ad[grow * H + head] = ab[tid * 2 + 1];
        }
    }

    // ---- C store ----
#pragma unroll
    for (int mi = 0; mi < 2; mi++) {
        int row = m0 + wm + mi * 16 + (lane >> 2);
#pragma unroll
        for (int ni = 0; ni < 8; ni++) {
            int col = n0 + wn + ni * 8 + (lane & 3) * 2;
            *(float2*)&C[(size_t)row * HF + col]       = make_float2(c[mi][ni][0], c[mi][ni][1]);
            *(float2*)&C[(size_t)(row + 8) * HF + col] = make_float2(c[mi][ni][2], c[mi][ni][3]);
        }
    }
}

// ================= fp32 -> bf16 hi/lo conversions =================
__global__ void conv_act_kernel(const float* __restrict__ src, int total) {
    int i = blockIdx.x * blockDim.x + threadIdx.x;
    if (i >= total) return;
    float v = src[i];
    __nv_bfloat16 h = __float2bfloat16(v);
    g_ah[i] = h;
    g_al[i] = __float2bfloat16(v - __bfloat162float(h));
}
// W: [K, HF] -> g_bh/g_bl: [HF, K], tiled transpose (coalesced both sides)
__global__ void conv_wt_kernel(const float* __restrict__ W, int K, int HF) {
    __shared__ float tile[32][33];
    int bx = blockIdx.x * 32;   // HF dim
    int by = blockIdx.y * 32;   // K dim
    int tx = threadIdx.x, ty = threadIdx.y;   // 32 x 8
#pragma unroll
    for (int r = 0; r < 32; r += 8)
        tile[ty + r][tx] = W[(size_t)(by + ty + r) * HF + bx + tx];
    __syncthreads();
#pragma unroll
    for (int r = 0; r < 32; r += 8) {
        float v = tile[tx][ty + r];
        __nv_bfloat16 h = __float2bfloat16(v);
        size_t o = (size_t)(bx + ty + r) * K + by + tx;
        g_bh[o] = h;
        g_bl[o] = __float2bfloat16(v - __bfloat162float(h));
    }
}

// ---------------- CSR build ----------------
__global__ void zero_cnt_kernel() {
    int i = blockIdx.x * blockDim.x + threadIdx.x;
    if (i < NN) g_cnt[i] = 0;
}
__global__ void count_kernel(const int* __restrict__ ei) {
    int i = blockIdx.x * blockDim.x + threadIdx.x;
    if (i < EE) atomicAdd(&g_cnt[ei[EE + i]], 1);
}
__global__ __launch_bounds__(1024) void scan_kernel() {
    __shared__ int sums[1024];
    const int C = 20;
    int t = threadIdx.x;
    int base = t * C;
    int s = 0;
    for (int i = 0; i < C; i++) {
        int idx = base + i;
        if (idx < NN) s += g_cnt[idx];
    }
    sums[t] = s;
    __syncthreads();
    for (int off = 1; off < 1024; off <<= 1) {
        int v = (t >= off) ? sums[t - off] : 0;
        __syncthreads();
        sums[t] += v;
        __syncthreads();
    }
    int run = (t == 0) ? 0 : sums[t - 1];
    for (int i = 0; i < C; i++) {
        int idx = base + i;
        if (idx < NN) { g_rowptr[idx] = run; run += g_cnt[idx]; }
    }
    if (t == 1023) g_rowptr[NN] = run;
}
__global__ void scatter_kernel(const int* __restrict__ ei) {
    int i = blockIdx.x * blockDim.x + threadIdx.x;
    if (i >= EE) return;
    int dst = ei[EE + i];
    int pos = g_rowptr[dst] + atomicAdd(&g_cnt[dst], 1);
    g_col[pos] = ei[i];
}

// ------- fused single-pass online-softmax aggregation: warp per (dst, head) -------
__global__ __launch_bounds__(256)
void gat_agg_kernel(const float* __restrict__ bias, int H, int F, int relu, int wsplit) {
    int gw   = (blockIdx.x * blockDim.x + threadIdx.x) >> 5;
    int lane = threadIdx.x & 31;
    if (gw >= NN * H) return;
    int dst = gw / H, h = gw - dst * H;
    int HF = H * F;

    int r0 = g_rowptr[dst], r1 = g_rowptr[dst + 1];
    float ad_d = g_ad[dst * H + h];
    float m    = leakyf(g_as[dst * H + h] + ad_d);   // self-loop logit
    float den  = 1.f;

    size_t fofs = (size_t)h * F + lane * 4;
    float4 acc = *(const float4*)&g_h[(size_t)dst * HF + fofs];

    int j = r0;
    for (; j + 4 <= r1; j += 4) {
        int s0 = g_col[j], s1 = g_col[j + 1], s2 = g_col[j + 2], s3 = g_col[j + 3];
        float e0 = leakyf(g_as[s0 * H + h] + ad_d);
        float e1 = leakyf(g_as[s1 * H + h] + ad_d);
        float e2 = leakyf(g_as[s2 * H + h] + ad_d);
        float e3 = leakyf(g_as[s3 * H + h] + ad_d);
        float4 v0 = *(const float4*)&g_h[(size_t)s0 * HF + fofs];
        float4 v1 = *(const float4*)&g_h[(size_t)s1 * HF + fofs];
        float4 v2 = *(const float4*)&g_h[(size_t)s2 * HF + fofs];
        float4 v3 = *(const float4*)&g_h[(size_t)s3 * HF + fofs];
        float mn = fmaxf(fmaxf(m, fmaxf(e0, e1)), fmaxf(e2, e3));
        float sc = __expf(m - mn);
        float w0 = __expf(e0 - mn), w1 = __expf(e1 - mn);
        float w2 = __expf(e2 - mn), w3 = __expf(e3 - mn);
        den = den * sc + (w0 + w1) + (w2 + w3);
        acc.x = acc.x * sc + (w0 * v0.x + w1 * v1.x) + (w2 * v2.x + w3 * v3.x);
        acc.y = acc.y * sc + (w0 * v0.y + w1 * v1.y) + (w2 * v2.y + w3 * v3.y);
        acc.z = acc.z * sc + (w0 * v0.z + w1 * v1.z) + (w2 * v2.z + w3 * v3.z);
        acc.w = acc.w * sc + (w0 * v0.w + w1 * v1.w) + (w2 * v2.w + w3 * v3.w);
        m = mn;
    }
    for (; j < r1; j++) {
        int s0 = g_col[j];
        float e0 = leakyf(g_as[s0 * H + h] + ad_d);
        float4 v0 = *(const float4*)&g_h[(size_t)s0 * HF + fofs];
        float mn = fmaxf(m, e0);
        float sc = __expf(m - mn);
        float w0 = __expf(e0 - mn);
        den = den * sc + w0;
        acc.x = acc.x * sc + w0 * v0.x;
        acc.y = acc.y * sc + w0 * v0.y;
        acc.z = acc.z * sc + w0 * v0.z;
        acc.w = acc.w * sc + w0 * v0.w;
        m = mn;
    }

    float inv = 1.f / den;
    float4 b4 = *(const float4*)&bias[h * F + lane * 4];
    acc.x = acc.x * inv + b4.x;
    acc.y = acc.y * inv + b4.y;
    acc.z = acc.z * inv + b4.z;
    acc.w = acc.w * inv + b4.w;
    if (relu) {
        acc.x = fmaxf(acc.x, 0.f); acc.y = fmaxf(acc.y, 0.f);
        acc.z = fmaxf(acc.z, 0.f); acc.w = fmaxf(acc.w, 0.f);
    }
    size_t oidx = (size_t)dst * HF + fofs;
    *(float4*)&g_out[oidx] = acc;

    if (wsplit) {
        __nv_bfloat16 hv[4], lv[4];
        float a[4] = {acc.x, acc.y, acc.z, acc.w};
#pragma unroll
        for (int q = 0; q < 4; q++) {
            hv[q] = __float2bfloat16(a[q]);
            lv[q] = __float2bfloat16(a[q] - __bfloat162float(hv[q]));
        }
        *(uint2*)&g_ah[oidx] = *(uint2*)hv;
        *(uint2*)&g_al[oidx] = *(uint2*)lv;
    }
}

// ---------------- mask flag + pooling ----------------
__global__ void flag_zero_kernel() { g_flag = 0; }
__global__ void flag_set_kernel(const int* __restrict__ mask) {
    int i = blockIdx.x * blockDim.x + threadIdx.x;
    if (i < NN && mask[i] != 0) g_flag = 1;
}
__global__ void pool_init_kernel(float* out) {
    int i = blockIdx.x * blockDim.x + threadIdx.x;
    if (i < BBATCH * 128) out[i] = -1e30f;
}
// grid 157 x 256 threads; sorted batch_id -> block-local running max, flush on boundary
__global__ __launch_bounds__(256)
void pool_kernel(const int* __restrict__ batch,
                 const int* __restrict__ mask,
                 float* __restrict__ out) {
    int f    = threadIdx.x & 127;
    int half = threadIdx.x >> 7;
    int base = blockIdx.x * 128 + half * 64;
    int flag = g_flag;
    int cur = -1;
    float lm = -3e38f;
    int end = base + 64;
    if (end > NN) end = NN;
    for (int n = base; n < end; n++) {
        int b = batch[n];
        if (b != cur) {
            if (cur >= 0) atomicMaxF(&out[cur * 128 + f], lm);
            cur = b;
            lm = -3e38f;
        }
        if (!(flag && mask[n] != 0))
            lm = fmaxf(lm, g_out[(size_t)n * 128 + f]);
    }
    if (cur >= 0) atomicMaxF(&out[cur * 128 + f], lm);
}

// ---------------- host side ----------------
static inline int cdiv(int a, int b) { return (a + b - 1) / b; }

static void run_layer(const float* W, const float* asrc,
                      const float* adst, const float* bias,
                      float* p_h, int Fin, int F, int H, int relu, int wsplit) {
    int HF = H * F;
    {
        dim3 tgrid(HF / 32, Fin / 32);
        conv_wt_kernel<<<tgrid, dim3(32, 8)>>>(W, Fin, HF);
    }
    {
        __nv_bfloat16 *pah, *pal, *pbh, *pbl;
        cudaGetSymbolAddress((void**)&pah, g_ah);
        cudaGetSymbolAddress((void**)&pal, g_al);
        cudaGetSymbolAddress((void**)&pbh, g_bh);
        cudaGetSymbolAddress((void**)&pbl, g_bl);
        dim3 grid(HF / 128, M_PAD / 128);
        mma_gemm_kernel<<<grid, 256, GEMM_SMEM>>>(pah, pal, pbh, pbl, p_h,
                                                  asrc, adst, Fin, HF, H);
    }
    gat_agg_kernel<<<cdiv(NN * H * 32, 256), 256>>>(bias, H, F, relu, wsplit);
}

extern "C" void kernel_launch(void* const* d_in, const int* in_sizes, int n_in,
                              void* d_out, int out_size) {
    const float* x     = (const float*)d_in[0];
    const int*   ei    = (const int*)d_in[1];
    const int*   batch = (const int*)d_in[2];
    const int*   nmask = (const int*)d_in[3];
    // d_in[4] = edge_mask (ignored: GATConv edge_dim=None)
    const float* W1 = (const float*)d_in[5];
    const float* as1 = (const float*)d_in[6];
    const float* ad1 = (const float*)d_in[7];
    const float* b1 = (const float*)d_in[8];
    const float* W2 = (const float*)d_in[9];
    const float* as2 = (const float*)d_in[10];
    const float* ad2 = (const float*)d_in[11];
    const float* b2 = (const float*)d_in[12];
    const float* W3 = (const float*)d_in[13];
    const float* as3 = (const float*)d_in[14];
    const float* ad3 = (const float*)d_in[15];
    const float* b3 = (const float*)d_in[16];

    cudaFuncSetAttribute(mma_gemm_kernel,
                         cudaFuncAttributeMaxDynamicSharedMemorySize, GEMM_SMEM);

    float* p_h = nullptr;
    cudaGetSymbolAddress((void**)&p_h, g_h);
    float* dout = (float*)d_out;

    // CSR build (by dst)
    zero_cnt_kernel<<<cdiv(NN, 256), 256>>>();
    count_kernel<<<cdiv(EE, 256), 256>>>(ei);
    scan_kernel<<<1, 1024>>>();
    zero_cnt_kernel<<<cdiv(NN, 256), 256>>>();
    scatter_kernel<<<cdiv(EE, 256), 256>>>(ei);

    // Layer 1: x -> bf16 split, then 128 -> 4x128, relu, emit split for layer 2
    conv_act_kernel<<<cdiv(NN * 128, 256), 256>>>(x, NN * 128);
    run_layer(W1, as1, ad1, b1, p_h, 128, 128, 4, 1, 1);
    // Layer 2: 512 -> 4x128, relu, emit split for layer 3
    run_layer(W2, as2, ad2, b2, p_h, 512, 128, 4, 1, 1);
    // Layer 3: 512 -> 1x128, no relu, no split
    run_layer(W3, as3, ad3, b3, p_h, 512, 128, 1, 0, 0);

    // Masked global max pool
    flag_zero_kernel<<<1, 1>>>();
    flag_set_kernel<<<cdiv(NN, 256), 256>>>(nmask);
    pool_init_kernel<<<cdiv(BBATCH * 128, 256), 256>>>(dout);
    pool_kernel<<<M_PAD / 128, 256>>>(batch, nmask, dout);
}

// round 7
// speedup vs baseline: 2.5863x; 1.0766x over previous
#include <cuda_runtime.h>
#include <cuda_bf16.h>
#include <math.h>
#include <stdint.h>

// Problem constants
#define NN 20000
#define EE 320000
#define BBATCH 16
#define NEG_SLOPE 0.2f
#define M_PAD 20096           // 157 * 128

// ---------------- scratch (static device globals: allocation-free) ----------------
__device__ float g_h[(size_t)M_PAD * 512];   // GEMM output h = x @ W (padded rows)
__device__ float g_out[(size_t)NN * 512];    // aggregated layer output
__device__ __nv_bfloat16 g_ah[(size_t)M_PAD * 512];  // activation hi
__device__ __nv_bfloat16 g_al[(size_t)M_PAD * 512];  // activation lo
__device__ __nv_bfloat16 g_bh[512 * 512];    // weight^T hi  [HF, K]
__device__ __nv_bfloat16 g_bl[512 * 512];    // weight^T lo
__device__ float g_as[NN * 4];
__device__ float g_ad[NN * 4];
__device__ int   g_cnt[NN];
__device__ int   g_rowptr[NN + 1];
__device__ int   g_col[EE];
__device__ int   g_flag;

__device__ __forceinline__ float leakyf(float x) { return x > 0.f ? x : NEG_SLOPE * x; }

__device__ __forceinline__ void atomicMaxF(float* addr, float v) {
    if (v >= 0.f) atomicMax((int*)addr, __float_as_int(v));
    else          atomicMin((unsigned int*)addr, __float_as_uint(v));
}

// ================= baseline-PTX tensor-core helpers =================
__device__ __forceinline__ uint32_t smem_u32(const void* p) {
    uint32_t a;
    asm("{ .reg .u64 t; cvta.to.shared.u64 t, %1; cvt.u32.u64 %0, t; }" : "=r"(a) : "l"(p));
    return a;
}
#define CP_COMMIT() asm volatile("cp.async.commit_group;" ::: "memory")
#define CP_WAIT1()  asm volatile("cp.async.wait_group 1;" ::: "memory")
__device__ __forceinline__ void cpa16(uint32_t dst, const void* src) {
    asm volatile("cp.async.cg.shared.global [%0], [%1], 16;" :: "r"(dst), "l"(src) : "memory");
}
__device__ __forceinline__ void ldm4(uint32_t* r, uint32_t addr) {
    asm volatile("ldmatrix.sync.aligned.m8n8.x4.shared.b16 {%0,%1,%2,%3}, [%4];"
                 : "=r"(r[0]), "=r"(r[1]), "=r"(r[2]), "=r"(r[3]) : "r"(addr));
}
__device__ __forceinline__ void mma_bf16(float* d, const uint32_t* a,
                                         uint32_t b0, uint32_t b1) {
    asm volatile("mma.sync.aligned.m16n8k16.row.col.f32.bf16.bf16.f32 "
                 "{%0,%1,%2,%3}, {%4,%5,%6,%7}, {%8,%9}, {%0,%1,%2,%3};"
                 : "+f"(d[0]), "+f"(d[1]), "+f"(d[2]), "+f"(d[3])
                 : "r"(a[0]), "r"(a[1]), "r"(a[2]), "r"(a[3]), "r"(b0), "r"(b1));
}

// ================= bf16 split GEMM (3-term) + fused alpha epilogue ================
#define KC 32
#define PITCH 40                 // 80 B rows -> ldmatrix conflict-free
#define TILEB (128 * PITCH * 2)  // 10240 bytes per tile
#define GEMM_SMEM (12 * TILEB)   // 3 stages x 4 tiles = 122880

__global__ __launch_bounds__(256)
void mma_gemm_kernel(const __nv_bfloat16* __restrict__ Ah,
                     const __nv_bfloat16* __restrict__ Al,
                     const __nv_bfloat16* __restrict__ Bh,
                     const __nv_bfloat16* __restrict__ Bl,
                     float* __restrict__ C,
                     const float* __restrict__ asrc,
                     const float* __restrict__ adst,
                     int K, int HF, int H) {
    extern __shared__ __align__(16) __nv_bfloat16 smem[];
    uint32_t s0 = smem_u32(smem);

    int tid  = threadIdx.x;
    int wid  = tid >> 5;
    int lane = tid & 31;
    int m0 = blockIdx.y * 128;
    int n0 = blockIdx.x * 128;
    int wm = (wid & 3) * 32;    // warp M offset
    int wn = (wid >> 2) * 64;   // warp N offset

    float c[2][8][4];
#pragma unroll
    for (int i = 0; i < 2; i++)
#pragma unroll
        for (int j = 0; j < 8; j++)
#pragma unroll
            for (int q = 0; q < 4; q++) c[i][j][q] = 0.f;

    const int KCH = K / KC;

    const __nv_bfloat16* gp0 = Ah + (size_t)m0 * K;
    const __nv_bfloat16* gp1 = Al + (size_t)m0 * K;
    const __nv_bfloat16* gp2 = Bh + (size_t)n0 * K;
    const __nv_bfloat16* gp3 = Bl + (size_t)n0 * K;

    auto load_chunk = [&](int kc, int stage) {
        const __nv_bfloat16* gp[4] = {gp0 + kc * KC, gp1 + kc * KC,
                                      gp2 + kc * KC, gp3 + kc * KC};
#pragma unroll
        for (int kind = 0; kind < 4; kind++) {
            uint32_t base = s0 + (uint32_t)(stage * 4 + kind) * TILEB;
            const __nv_bfloat16* g = gp[kind];
#pragma unroll
            for (int r = 0; r < 2; r++) {
                int i = tid + r * 256;           // 0..511
                int row = i >> 2, seg = i & 3;   // 4 x 16B per 32-elem row
                cpa16(base + (uint32_t)(row * PITCH + seg * 8) * 2,
                      g + (size_t)row * K + seg * 8);
            }
        }
        CP_COMMIT();
    };

    load_chunk(0, 0);
    load_chunk(1, 1);

    int lr = lane & 15, ls = (lane >> 4) * 8;
    for (int t = 0; t < KCH; t++) {
        CP_WAIT1();
        __syncthreads();
        if (t + 2 < KCH) load_chunk(t + 2, (t + 2) % 3);
        else             CP_COMMIT();

        int stage = t % 3;
        uint32_t bAh = s0 + (uint32_t)(stage * 4 + 0) * TILEB;
        uint32_t bAl = s0 + (uint32_t)(stage * 4 + 1) * TILEB;
        uint32_t bBh = s0 + (uint32_t)(stage * 4 + 2) * TILEB;
        uint32_t bBl = s0 + (uint32_t)(stage * 4 + 3) * TILEB;
#pragma unroll
        for (int ks = 0; ks < 2; ks++) {
            int k0 = ks * 16;
            uint32_t ah[2][4], al[2][4], bt[4][4];
#pragma unroll
            for (int mi = 0; mi < 2; mi++)
                ldm4(ah[mi], bAh + (uint32_t)((wm + mi * 16 + lr) * PITCH + k0 + ls) * 2);
#pragma unroll
            for (int mi = 0; mi < 2; mi++)
                ldm4(al[mi], bAl + (uint32_t)((wm + mi * 16 + lr) * PITCH + k0 + ls) * 2);
#pragma unroll
            for (int ni = 0; ni < 4; ni++)
                ldm4(bt[ni], bBh + (uint32_t)((wn + ni * 16 + lr) * PITCH + k0 + ls) * 2);
#pragma unroll
            for (int mi = 0; mi < 2; mi++)
#pragma unroll
                for (int ni = 0; ni < 4; ni++) {
                    mma_bf16(c[mi][ni * 2],     ah[mi], bt[ni][0], bt[ni][2]);
                    mma_bf16(c[mi][ni * 2 + 1], ah[mi], bt[ni][1], bt[ni][3]);
                    mma_bf16(c[mi][ni * 2],     al[mi], bt[ni][0], bt[ni][2]);
                    mma_bf16(c[mi][ni * 2 + 1], al[mi], bt[ni][1], bt[ni][3]);
                }
#pragma unroll
            for (int ni = 0; ni < 4; ni++)
                ldm4(bt[ni], bBl + (uint32_t)((wn + ni * 16 + lr) * PITCH + k0 + ls) * 2);
#pragma unroll
            for (int mi = 0; mi < 2; mi++)
#pragma unroll
                for (int ni = 0; ni < 4; ni++) {
                    mma_bf16(c[mi][ni * 2],     ah[mi], bt[ni][0], bt[ni][2]);
                    mma_bf16(c[mi][ni * 2 + 1], ah[mi], bt[ni][1], bt[ni][3]);
                }
        }
    }
    __syncthreads();   // all compute done; smem reusable

    // ---- alpha epilogue ----
    float* ab = (float*)smem;
    ab[tid] = 0.f;
    __syncthreads();
    {
        float ps[2][2] = {{0.f, 0.f}, {0.f, 0.f}};
        float pd[2][2] = {{0.f, 0.f}, {0.f, 0.f}};
#pragma unroll
        for (int ni = 0; ni < 4; ni++) {
#pragma unroll
            for (int q2 = 0; q2 < 2; q2++) {
                int gc = n0 + wn + ni * 16 + q2 * 8 + (lane & 3) * 2;
                float a0 = asrc[gc], a1 = asrc[gc + 1];
                float d0 = adst[gc], d1 = adst[gc + 1];
#pragma unroll
                for (int mi = 0; mi < 2; mi++) {
                    const float* cc = c[mi][ni * 2 + q2];
                    ps[mi][0] += cc[0] * a0 + cc[1] * a1;
                    pd[mi][0] += cc[0] * d0 + cc[1] * d1;
                    ps[mi][1] += cc[2] * a0 + cc[3] * a1;
                    pd[mi][1] += cc[2] * d0 + cc[3] * d1;
                }
            }
        }
#pragma unroll
        for (int o = 1; o <= 2; o <<= 1)
#pragma unroll
            for (int mi = 0; mi < 2; mi++)
#pragma unroll
                for (int hf = 0; hf < 2; hf++) {
                    ps[mi][hf] += __shfl_xor_sync(0xffffffffu, ps[mi][hf], o);
                    pd[mi][hf] += __shfl_xor_sync(0xffffffffu, pd[mi][hf], o);
                }
        if ((lane & 3) == 0) {
#pragma unroll
            for (int mi = 0; mi < 2; mi++)
#pragma unroll
                for (int hf = 0; hf < 2; hf++) {
                    int row = wm + mi * 16 + (lane >> 2) + hf * 8;
                    atomicAdd(&ab[row * 2],     ps[mi][hf]);
                    atomicAdd(&ab[row * 2 + 1], pd[mi][hf]);
                }
        }
    }
    __syncthreads();
    if (tid < 128) {
        int grow = m0 + tid;
        if (grow < NN) {
            int head = n0 >> 7;
            g_as[grow * H + head] = ab[tid * 2];
            g_ad[grow * H + head] = ab[tid * 2 + 1];
        }
    }

    // ---- C store ----
#pragma unroll
    for (int mi = 0; mi < 2; mi++) {
        int row = m0 + wm + mi * 16 + (lane >> 2);
#pragma unroll
        for (int ni = 0; ni < 8; ni++) {
            int col = n0 + wn + ni * 8 + (lane & 3) * 2;
            *(float2*)&C[(size_t)row * HF + col]       = make_float2(c[mi][ni][0], c[mi][ni][1]);
            *(float2*)&C[(size_t)(row + 8) * HF + col] = make_float2(c[mi][ni][2], c[mi][ni][3]);
        }
    }
}

// ================= fp32 -> bf16 hi/lo conversions =================
__global__ void conv_act_kernel(const float* __restrict__ src, int total) {
    int i = blockIdx.x * blockDim.x + threadIdx.x;
    if (i >= total) return;
    float v = src[i];
    __nv_bfloat16 h = __float2bfloat16(v);
    g_ah[i] = h;
    g_al[i] = __float2bfloat16(v - __bfloat162float(h));
}
// W: [K, HF] -> g_bh/g_bl: [HF, K], tiled transpose
__global__ void conv_wt_kernel(const float* __restrict__ W, int K, int HF) {
    __shared__ float tile[32][33];
    int bx = blockIdx.x * 32;   // HF dim
    int by = blockIdx.y * 32;   // K dim
    int tx = threadIdx.x, ty = threadIdx.y;   // 32 x 8
#pragma unroll
    for (int r = 0; r < 32; r += 8)
        tile[ty + r][tx] = W[(size_t)(by + ty + r) * HF + bx + tx];
    __syncthreads();
#pragma unroll
    for (int r = 0; r < 32; r += 8) {
        float v = tile[tx][ty + r];
        __nv_bfloat16 h = __float2bfloat16(v);
        size_t o = (size_t)(bx + ty + r) * K + by + tx;
        g_bh[o] = h;
        g_bl[o] = __float2bfloat16(v - __bfloat162float(h));
    }
}

// ---------------- CSR build ----------------
__global__ void zero_cnt_kernel() {
    int i = blockIdx.x * blockDim.x + threadIdx.x;
    if (i < NN) g_cnt[i] = 0;
}
__global__ void count_kernel(const int* __restrict__ ei) {
    int i = blockIdx.x * blockDim.x + threadIdx.x;
    if (i < EE) atomicAdd(&g_cnt[ei[EE + i]], 1);
}
// scan also zeroes g_cnt (read then reset), so scatter can reuse it as cursor
__global__ __launch_bounds__(1024) void scan_kernel() {
    __shared__ int sums[1024];
    const int C = 20;
    int t = threadIdx.x;
    int base = t * C;
    int loc[C];
    int s = 0;
    for (int i = 0; i < C; i++) {
        int idx = base + i;
        loc[i] = (idx < NN) ? g_cnt[idx] : 0;
        if (idx < NN) g_cnt[idx] = 0;
        s += loc[i];
    }
    sums[t] = s;
    __syncthreads();
    for (int off = 1; off < 1024; off <<= 1) {
        int v = (t >= off) ? sums[t - off] : 0;
        __syncthreads();
        sums[t] += v;
        __syncthreads();
    }
    int run = (t == 0) ? 0 : sums[t - 1];
    for (int i = 0; i < C; i++) {
        int idx = base + i;
        if (idx < NN) { g_rowptr[idx] = run; run += loc[i]; }
    }
    if (t == 1023) g_rowptr[NN] = run;
}
__global__ void scatter_kernel(const int* __restrict__ ei) {
    int i = blockIdx.x * blockDim.x + threadIdx.x;
    if (i >= EE) return;
    int dst = ei[EE + i];
    int pos = g_rowptr[dst] + atomicAdd(&g_cnt[dst], 1);
    g_col[pos] = ei[i];
}

// ------- fused single-pass online-softmax aggregation: warp per (dst, head) -------
__global__ __launch_bounds__(256)
void gat_agg_kernel(const float* __restrict__ bias, int H, int F, int relu, int wsplit) {
    int gw   = (blockIdx.x * blockDim.x + threadIdx.x) >> 5;
    int lane = threadIdx.x & 31;
    if (gw >= NN * H) return;
    int dst = gw / H, h = gw - dst * H;
    int HF = H * F;

    int r0 = g_rowptr[dst], r1 = g_rowptr[dst + 1];
    float ad_d = g_ad[dst * H + h];
    float m    = leakyf(g_as[dst * H + h] + ad_d);
    float den  = 1.f;

    size_t fofs = (size_t)h * F + lane * 4;
    float4 acc = *(const float4*)&g_h[(size_t)dst * HF + fofs];

    int j = r0;
    for (; j + 4 <= r1; j += 4) {
        int s0 = g_col[j], s1 = g_col[j + 1], s2 = g_col[j + 2], s3 = g_col[j + 3];
        float e0 = leakyf(g_as[s0 * H + h] + ad_d);
        float e1 = leakyf(g_as[s1 * H + h] + ad_d);
        float e2 = leakyf(g_as[s2 * H + h] + ad_d);
        float e3 = leakyf(g_as[s3 * H + h] + ad_d);
        float4 v0 = *(const float4*)&g_h[(size_t)s0 * HF + fofs];
        float4 v1 = *(const float4*)&g_h[(size_t)s1 * HF + fofs];
        float4 v2 = *(const float4*)&g_h[(size_t)s2 * HF + fofs];
        float4 v3 = *(const float4*)&g_h[(size_t)s3 * HF + fofs];
        float mn = fmaxf(fmaxf(m, fmaxf(e0, e1)), fmaxf(e2, e3));
        float sc = __expf(m - mn);
        float w0 = __expf(e0 - mn), w1 = __expf(e1 - mn);
        float w2 = __expf(e2 - mn), w3 = __expf(e3 - mn);
        den = den * sc + (w0 + w1) + (w2 + w3);
        acc.x = acc.x * sc + (w0 * v0.x + w1 * v1.x) + (w2 * v2.x + w3 * v3.x);
        acc.y = acc.y * sc + (w0 * v0.y + w1 * v1.y) + (w2 * v2.y + w3 * v3.y);
        acc.z = acc.z * sc + (w0 * v0.z + w1 * v1.z) + (w2 * v2.z + w3 * v3.z);
        acc.w = acc.w * sc + (w0 * v0.w + w1 * v1.w) + (w2 * v2.w + w3 * v3.w);
        m = mn;
    }
    for (; j < r1; j++) {
        int s0 = g_col[j];
        float e0 = leakyf(g_as[s0 * H + h] + ad_d);
        float4 v0 = *(const float4*)&g_h[(size_t)s0 * HF + fofs];
        float mn = fmaxf(m, e0);
        float sc = __expf(m - mn);
        float w0 = __expf(e0 - mn);
        den = den * sc + w0;
        acc.x = acc.x * sc + w0 * v0.x;
        acc.y = acc.y * sc + w0 * v0.y;
        acc.z = acc.z * sc + w0 * v0.z;
        acc.w = acc.w * sc + w0 * v0.w;
        m = mn;
    }

    float inv = 1.f / den;
    float4 b4 = *(const float4*)&bias[h * F + lane * 4];
    acc.x = acc.x * inv + b4.x;
    acc.y = acc.y * inv + b4.y;
    acc.z = acc.z * inv + b4.z;
    acc.w = acc.w * inv + b4.w;
    if (relu) {
        acc.x = fmaxf(acc.x, 0.f); acc.y = fmaxf(acc.y, 0.f);
        acc.z = fmaxf(acc.z, 0.f); acc.w = fmaxf(acc.w, 0.f);
    }
    size_t oidx = (size_t)dst * HF + fofs;
    *(float4*)&g_out[oidx] = acc;

    if (wsplit) {
        __nv_bfloat16 hv[4], lv[4];
        float a[4] = {acc.x, acc.y, acc.z, acc.w};
#pragma unroll
        for (int q = 0; q < 4; q++) {
            hv[q] = __float2bfloat16(a[q]);
            lv[q] = __float2bfloat16(a[q] - __bfloat162float(hv[q]));
        }
        *(uint2*)&g_ah[oidx] = *(uint2*)hv;
        *(uint2*)&g_al[oidx] = *(uint2*)lv;
    }
}

// ---------------- mask flag + pooling ----------------
__global__ void flag_zero_kernel() { g_flag = 0; }
__global__ void flag_set_kernel(const int* __restrict__ mask) {
    int i = blockIdx.x * blockDim.x + threadIdx.x;
    if (i < NN && mask[i] != 0) g_flag = 1;
}
__global__ void pool_init_kernel(float* out) {
    int i = blockIdx.x * blockDim.x + threadIdx.x;
    if (i < BBATCH * 128) out[i] = -1e30f;
}
__global__ __launch_bounds__(256)
void pool_kernel(const int* __restrict__ batch,
                 const int* __restrict__ mask,
                 float* __restrict__ out) {
    int f    = threadIdx.x & 127;
    int half = threadIdx.x >> 7;
    int base = blockIdx.x * 128 + half * 64;
    int flag = g_flag;
    int cur = -1;
    float lm = -3e38f;
    int end = base + 64;
    if (end > NN) end = NN;
    for (int n = base; n < end; n++) {
        int b = batch[n];
        if (b != cur) {
            if (cur >= 0) atomicMaxF(&out[cur * 128 + f], lm);
            cur = b;
            lm = -3e38f;
        }
        if (!(flag && mask[n] != 0))
            lm = fmaxf(lm, g_out[(size_t)n * 128 + f]);
    }
    if (cur >= 0) atomicMaxF(&out[cur * 128 + f], lm);
}

// ---------------- host side ----------------
static inline int cdiv(int a, int b) { return (a + b - 1) / b; }

static void launch_conv_wt(const float* W, int Fin, int HF, cudaStream_t s) {
    dim3 tgrid(HF / 32, Fin / 32);
    conv_wt_kernel<<<tgrid, dim3(32, 8), 0, s>>>(W, Fin, HF);
}
static void launch_gemm(float* p_h, const float* asrc, const float* adst,
                        int Fin, int HF, int H) {
    __nv_bfloat16 *pah, *pal, *pbh, *pbl;
    cudaGetSymbolAddress((void**)&pah, g_ah);
    cudaGetSymbolAddress((void**)&pal, g_al);
    cudaGetSymbolAddress((void**)&pbh, g_bh);
    cudaGetSymbolAddress((void**)&pbl, g_bl);
    dim3 grid(HF / 128, M_PAD / 128);
    mma_gemm_kernel<<<grid, 256, GEMM_SMEM>>>(pah, pal, pbh, pbl, p_h,
                                              asrc, adst, Fin, HF, H);
}

extern "C" void kernel_launch(void* const* d_in, const int* in_sizes, int n_in,
                              void* d_out, int out_size) {
    const float* x     = (const float*)d_in[0];
    const int*   ei    = (const int*)d_in[1];
    const int*   batch = (const int*)d_in[2];
    const int*   nmask = (const int*)d_in[3];
    // d_in[4] = edge_mask (ignored: GATConv edge_dim=None)
    const float* W1 = (const float*)d_in[5];
    const float* as1 = (const float*)d_in[6];
    const float* ad1 = (const float*)d_in[7];
    const float* b1 = (const float*)d_in[8];
    const float* W2 = (const float*)d_in[9];
    const float* as2 = (const float*)d_in[10];
    const float* ad2 = (const float*)d_in[11];
    const float* b2 = (const float*)d_in[12];
    const float* W3 = (const float*)d_in[13];
    const float* as3 = (const float*)d_in[14];
    const float* ad3 = (const float*)d_in[15];
    const float* b3 = (const float*)d_in[16];

    cudaFuncSetAttribute(mma_gemm_kernel,
                         cudaFuncAttributeMaxDynamicSharedMemorySize, GEMM_SMEM);

    float* p_h = nullptr;
    cudaGetSymbolAddress((void**)&p_h, g_h);
    float* dout = (float*)d_out;

    cudaStream_t aux;
    cudaStreamCreateWithFlags(&aux, cudaStreamNonBlocking);
    cudaEvent_t evFork, evCsr, evG1, evW2, evG2, evW3;
    cudaEventCreateWithFlags(&evFork, cudaEventDisableTiming);
    cudaEventCreateWithFlags(&evCsr,  cudaEventDisableTiming);
    cudaEventCreateWithFlags(&evG1,   cudaEventDisableTiming);
    cudaEventCreateWithFlags(&evW2,   cudaEventDisableTiming);
    cudaEventCreateWithFlags(&evG2,   cudaEventDisableTiming);
    cudaEventCreateWithFlags(&evW3,   cudaEventDisableTiming);

    // ---- fork: aux handles CSR build + flag + pool init, concurrent with
    //      conv_act / conv_wt1 / GEMM1 on the main (legacy) stream ----
    cudaEventRecord(evFork, 0);
    cudaStreamWaitEvent(aux, evFork, 0);

    zero_cnt_kernel<<<cdiv(NN, 256), 256, 0, aux>>>();
    count_kernel<<<cdiv(EE, 256), 256, 0, aux>>>(ei);
    scan_kernel<<<1, 1024, 0, aux>>>();            // also re-zeroes g_cnt
    scatter_kernel<<<cdiv(EE, 256), 256, 0, aux>>>(ei);
    flag_zero_kernel<<<1, 1, 0, aux>>>();
    flag_set_kernel<<<cdiv(NN, 256), 256, 0, aux>>>(nmask);
    pool_init_kernel<<<cdiv(BBATCH * 128, 256), 256, 0, aux>>>(dout);
    cudaEventRecord(evCsr, aux);

    // ---- main chain: layer 1 ----
    conv_act_kernel<<<cdiv(NN * 128, 256), 256>>>(x, NN * 128);
    launch_conv_wt(W1, 128, 512, 0);
    launch_gemm(p_h, as1, ad1, 128, 512, 4);
    cudaEventRecord(evG1, 0);

    // aux: weight conversion for layer 2, concurrent with agg1
    cudaStreamWaitEvent(aux, evG1, 0);
    launch_conv_wt(W2, 512, 512, aux);
    cudaEventRecord(evW2, aux);

    cudaStreamWaitEvent(0, evCsr, 0);              // CSR ready before aggregation
    gat_agg_kernel<<<cdiv(NN * 4 * 32, 256), 256>>>(b1, 4, 128, 1, 1);

    // ---- layer 2 ----
    cudaStreamWaitEvent(0, evW2, 0);
    launch_gemm(p_h, as2, ad2, 512, 512, 4);
    cudaEventRecord(evG2, 0);

    cudaStreamWaitEvent(aux, evG2, 0);
    launch_conv_wt(W3, 512, 128, aux);
    cudaEventRecord(evW3, aux);

    gat_agg_kernel<<<cdiv(NN * 4 * 32, 256), 256>>>(b2, 4, 128, 1, 1);

    // ---- layer 3 ----
    cudaStreamWaitEvent(0, evW3, 0);
    launch_gemm(p_h, as3, ad3, 512, 128, 1);
    gat_agg_kernel<<<cdiv(NN * 1 * 32, 256), 256>>>(b3, 1, 128, 0, 0);

    // ---- masked global max pool (pool_init + flag joined via evCsr) ----
    pool_kernel<<<M_PAD / 128, 256>>>(batch, nmask, dout);

    cudaEventDestroy(evFork); cudaEventDestroy(evCsr);
    cudaEventDestroy(evG1);   cudaEventDestroy(evW2);
    cudaEventDestroy(evG2);   cudaEventDestroy(evW3);
    cudaStreamDestroy(aux);
}